// round 4
// baseline (speedup 1.0000x reference)
#include <cuda_runtime.h>

// ============================================================================
// EcgFilter — round 2: coalesce the IIR filtfilt.
//
// Pipeline:
//   A  : transpose x (384 x 120000) -> xT (120000 x 384)
//   B1 : IIR forward phase1  (zero-state chunk runs, transposed/coalesced)
//   B2 : IIR forward scan    (per-row affine scan over 128 chunk maps)
//   B3 : IIR forward phase2  -> yfT (ext coords, transposed)
//   B4 : IIR backward phase1 (on reversed yfT)
//   B5 : IIR backward scan
//   B6 : IIR backward phase2 -> g_mid ROW-MAJOR via per-warp smem transpose
//   C  : g = autocorr(b_fir)  (FIR filtfilt == single symmetric 301-tap conv)
//   D  : 301-tap conv on odd-extended g_mid -> out   (unchanged, fma-bound)
// ============================================================================

#define T_LEN   120000
#define N_ROWS  384
#define EDGE    9
#define TEXT    (T_LEN + 2*EDGE)             // 120018
#define P_CH    128                          // time chunks per row
#define L_CH    938                          // ceil(TEXT / P_CH)
#define RG      (N_ROWS / 32)                // 12 row-groups of 32
#define IIR_WARPS (RG * P_CH)                // 1536
#define IIR_BLOCKS (IIR_WARPS / 8)           // 192 blocks of 256 threads

#define FIR_TAPS 151
#define G_TAPS   301
#define HALO     150
#define F_THREADS 256
#define F_RPT     8
#define F_TILE    (F_THREADS * F_RPT)        // 2048
#define F_SM      (F_TILE + 2*HALO + 8)      // 2356

// ---------------- scratch (static __device__: allocation-free rule) --------
__device__ float g_xT [(size_t)T_LEN * N_ROWS];   // transposed input
__device__ float g_yfT[(size_t)TEXT  * N_ROWS];   // forward IIR out (ext, transposed)
__device__ float g_mid[(size_t)N_ROWS * T_LEN];   // IIR filtfilt out (row-major)
__device__ float g_V1[P_CH * N_ROWS], g_V2[P_CH * N_ROWS];
__device__ float g_Z1[P_CH * N_ROWS], g_Z2[P_CH * N_ROWS];
__device__ float g_comb[G_TAPS];

// odd extension read, row-major row pointer (used by FIR kernel)
__device__ __forceinline__ float odd_ext_load(const float* __restrict__ r, int u)
{
    if (u < 0)       return 2.0f * r[0]         - r[-u];
    if (u >= T_LEN)  return 2.0f * r[T_LEN - 1] - r[2 * T_LEN - 2 - u];
    return r[u];
}

// odd extension read in transposed layout: ext index i in [0, TEXT)
__device__ __forceinline__ float xT_ext(int i, int r)
{
    int u = i - EDGE;
    if (u < 0)
        return 2.0f * g_xT[r] - g_xT[(size_t)(-u) * N_ROWS + r];
    if (u >= T_LEN)
        return 2.0f * g_xT[(size_t)(T_LEN - 1) * N_ROWS + r]
             -        g_xT[(size_t)(2 * T_LEN - 2 - u) * N_ROWS + r];
    return g_xT[(size_t)u * N_ROWS + r];
}

// ============================================================================
// A: transpose (row, t) -> (t, row)
// ============================================================================
__global__ __launch_bounds__(256)
void transpose_kernel(const float* __restrict__ x)
{
    __shared__ float tile[32][33];
    const int tbase = blockIdx.x * 32;
    const int rbase = blockIdx.y * 32;
    const int tx = threadIdx.x, ty = threadIdx.y;   // 32 x 8
    #pragma unroll
    for (int j = 0; j < 32; j += 8)
        tile[ty + j][tx] = x[(size_t)(rbase + ty + j) * T_LEN + tbase + tx];
    __syncthreads();
    #pragma unroll
    for (int j = 0; j < 32; j += 8)
        g_xT[(size_t)(tbase + ty + j) * N_ROWS + rbase + tx] = tile[tx][ty + j];
}

// ============================================================================
// B1/B4: phase1 — zero-state chunk run. warp = (row-group, chunk).
// FWD: stream = odd-ext(x);  !FWD: stream = reversed yfT.
// ============================================================================
template<bool FWD>
__global__ __launch_bounds__(256)
void iir_phase1(const float* __restrict__ b, const float* __restrict__ a)
{
    const int w    = (blockIdx.x * 256 + threadIdx.x) >> 5;
    const int lane = threadIdx.x & 31;
    const int p    = w % P_CH;
    const int rg   = w / P_CH;
    const int r    = rg * 32 + lane;

    const float b0 = b[0], b1 = b[1], b2 = b[2];
    const float a1 = a[1], a2 = a[2];

    const int s = p * L_CH;
    int len = TEXT - s; len = len < L_CH ? len : L_CH;

    float z1 = 0.f, z2 = 0.f;
    for (int i = s; i < s + len; ++i) {
        float xn = FWD ? xT_ext(i, r)
                       : g_yfT[(size_t)(TEXT - 1 - i) * N_ROWS + r];
        float y  = fmaf(b0, xn, z1);
        float n1 = fmaf(b1, xn, z2) - a1 * y;
        float n2 = b2 * xn - a2 * y;
        z1 = n1; z2 = n2;
    }
    g_V1[p * N_ROWS + r] = z1;
    g_V2[p * N_ROWS + r] = z2;
}

// ============================================================================
// B2/B5: scan — one block, 384 threads. Threads < 128 build M_p = A^len(p)
// (depends only on p), then every thread serially scans its row's 128 chunks.
// ============================================================================
__global__ __launch_bounds__(N_ROWS)
void iir_scan(const float* __restrict__ a, const float* __restrict__ zi,
              int backward)
{
    __shared__ float m00[P_CH], m01[P_CH], m10[P_CH], m11[P_CH];
    const int tid = threadIdx.x;
    const float a1 = a[1], a2 = a[2];

    if (tid < P_CH) {
        int s = tid * L_CH;
        int len = TEXT - s; len = len < L_CH ? len : L_CH;
        float c00 = -a1, c01 = 1.f, c10 = -a2, c11 = 0.f;
        float r00 = 1.f, r01 = 0.f, r10 = 0.f, r11 = 1.f;
        int e = len;
        while (e) {
            if (e & 1) {
                float t00 = r00*c00 + r01*c10, t01 = r00*c01 + r01*c11;
                float t10 = r10*c00 + r11*c10, t11 = r10*c01 + r11*c11;
                r00 = t00; r01 = t01; r10 = t10; r11 = t11;
            }
            e >>= 1;
            if (e) {
                float t00 = c00*c00 + c01*c10, t01 = c00*c01 + c01*c11;
                float t10 = c10*c00 + c11*c10, t11 = c10*c01 + c11*c11;
                c00 = t00; c01 = t01; c10 = t10; c11 = t11;
            }
        }
        m00[tid] = r00; m01[tid] = r01; m10[tid] = r10; m11[tid] = r11;
    }
    __syncthreads();

    const int r = tid;
    float e0 = backward ? g_yfT[(size_t)(TEXT - 1) * N_ROWS + r]
                        : xT_ext(0, r);
    float z1 = zi[0] * e0, z2 = zi[1] * e0;
    for (int p = 0; p < P_CH; ++p) {
        g_Z1[p * N_ROWS + r] = z1;
        g_Z2[p * N_ROWS + r] = z2;
        float v1 = g_V1[p * N_ROWS + r];
        float v2 = g_V2[p * N_ROWS + r];
        float n1 = m00[p]*z1 + m01[p]*z2 + v1;
        float n2 = m10[p]*z1 + m11[p]*z2 + v2;
        z1 = n1; z2 = n2;
    }
}

// ============================================================================
// B3: forward phase2 — rerun with correct state, emit yfT (coalesced)
// ============================================================================
__global__ __launch_bounds__(256)
void iir_phase2_fwd(const float* __restrict__ b, const float* __restrict__ a)
{
    const int w    = (blockIdx.x * 256 + threadIdx.x) >> 5;
    const int lane = threadIdx.x & 31;
    const int p    = w % P_CH;
    const int rg   = w / P_CH;
    const int r    = rg * 32 + lane;

    const float b0 = b[0], b1 = b[1], b2 = b[2];
    const float a1 = a[1], a2 = a[2];

    const int s = p * L_CH;
    int len = TEXT - s; len = len < L_CH ? len : L_CH;

    float z1 = g_Z1[p * N_ROWS + r];
    float z2 = g_Z2[p * N_ROWS + r];
    for (int i = s; i < s + len; ++i) {
        float xn = xT_ext(i, r);
        float y  = fmaf(b0, xn, z1);
        g_yfT[(size_t)i * N_ROWS + r] = y;
        float n1 = fmaf(b1, xn, z2) - a1 * y;
        float n2 = b2 * xn - a2 * y;
        z1 = n1; z2 = n2;
    }
}

// ============================================================================
// B6: backward phase2 — rerun reversed stream, write final trimmed result
// ROW-MAJOR to g_mid via per-warp 32x32 smem transpose staging.
// final index t = TEXT-10-i; keep 0 <= t < T_LEN.
// ============================================================================
__global__ __launch_bounds__(256)
void iir_phase2_bwd(const float* __restrict__ b, const float* __restrict__ a)
{
    __shared__ float stile[8][32][33];
    const int wib  = threadIdx.x >> 5;
    float (*sS)[33] = stile[wib];

    const int w    = (blockIdx.x * 256 + threadIdx.x) >> 5;
    const int lane = threadIdx.x & 31;
    const int p    = w % P_CH;
    const int rg   = w / P_CH;
    const int r    = rg * 32 + lane;
    const int rowbase = rg * 32;

    const float b0 = b[0], b1 = b[1], b2 = b[2];
    const float a1 = a[1], a2 = a[2];

    const int s = p * L_CH;
    int len = TEXT - s; len = len < L_CH ? len : L_CH;

    float z1 = g_Z1[p * N_ROWS + r];
    float z2 = g_Z2[p * N_ROWS + r];

    int i = s;
    while (i < s + len) {
        const int ib  = i;
        int cnt = s + len - ib; cnt = cnt < 32 ? cnt : 32;
        for (int c = 0; c < cnt; ++c, ++i) {
            float xn = g_yfT[(size_t)(TEXT - 1 - i) * N_ROWS + r];
            float y  = fmaf(b0, xn, z1);
            float n1 = fmaf(b1, xn, z2) - a1 * y;
            float n2 = b2 * xn - a2 * y;
            z1 = n1; z2 = n2;
            sS[lane][c] = y;
        }
        __syncwarp();
        const int t_ib = TEXT - 10 - ib;         // t for column 0
        const int t2 = t_ib - lane;              // column lane -> this t
        const bool ok = (lane < cnt) && (t2 >= 0) && (t2 < T_LEN);
        #pragma unroll 4
        for (int rr = 0; rr < 32; ++rr) {
            float v = sS[rr][lane];
            if (ok) g_mid[(size_t)(rowbase + rr) * T_LEN + t2] = v;
        }
        __syncwarp();
    }
}

// ============================================================================
// C: g[d] = autocorrelation of b_fir
// ============================================================================
__global__ void comb_kernel(const float* __restrict__ bf)
{
    int k = threadIdx.x;
    if (k >= G_TAPS) return;
    int d  = k - HALO;
    int j0 = d < 0 ? -d : 0;
    int j1 = d < 0 ? (FIR_TAPS - 1) : (FIR_TAPS - 1 - d);
    float acc = 0.f;
    for (int j = j0; j <= j1; ++j)
        acc = fmaf(bf[j], bf[j + d], acc);
    g_comb[k] = acc;
}

// ============================================================================
// D: symmetric 301-tap convolution on odd-extended g_mid -> out (unchanged)
// ============================================================================
__global__ __launch_bounds__(F_THREADS)
void fir_kernel(float* __restrict__ out)
{
    __shared__ float sT[F_SM];
    __shared__ float sG[G_TAPS];

    const int row = blockIdx.y;
    const int t0  = blockIdx.x * F_TILE;
    const float* xr   = g_mid + (size_t)row * T_LEN;
    float*       outr = out   + (size_t)row * T_LEN;

    for (int j = threadIdx.x; j < F_TILE + 2 * HALO; j += F_THREADS)
        sT[j] = odd_ext_load(xr, t0 - HALO + j);
    for (int j = threadIdx.x; j < G_TAPS; j += F_THREADS)
        sG[j] = g_comb[j];
    __syncthreads();

    const int base = threadIdx.x * F_RPT;
    float acc[F_RPT];
    float w[F_RPT];
    #pragma unroll
    for (int r = 0; r < F_RPT; ++r) { acc[r] = 0.f; w[r] = sT[base + r]; }

    #pragma unroll 1
    for (int kb = 0; kb < 296; kb += 8) {
        #pragma unroll
        for (int kk = 0; kk < 8; ++kk) {
            float gk = sG[kb + kk];
            #pragma unroll
            for (int r = 0; r < F_RPT; ++r)
                acc[r] = fmaf(gk, w[(r + kk) & 7], acc[r]);
            w[kk] = sT[base + kb + kk + 8];
        }
    }
    #pragma unroll
    for (int k = 296; k < G_TAPS; ++k) {
        float gk = sG[k];
        #pragma unroll
        for (int r = 0; r < F_RPT; ++r)
            acc[r] = fmaf(gk, sT[base + k + r], acc[r]);
    }

    const int tg = t0 + base;
    #pragma unroll
    for (int r = 0; r < F_RPT; ++r) {
        int t = tg + r;
        if (t < T_LEN) outr[t] = acc[r];
    }
}

// ============================================================================
// Inputs (metadata order): x, b_notch(3), a_notch(3), zi_notch(2),
//                          b_fir(151), zi_fir (provably unused: both FIR
//                          filtfilt zi corrections land in trimmed regions)
// ============================================================================
extern "C" void kernel_launch(void* const* d_in, const int* in_sizes, int n_in,
                              void* d_out, int out_size)
{
    const float* x  = (const float*)d_in[0];
    const float* bn = (const float*)d_in[1];
    const float* an = (const float*)d_in[2];
    const float* zn = (const float*)d_in[3];
    const float* bf = (const float*)d_in[4];
    float* out = (float*)d_out;

    dim3 tgrid(T_LEN / 32, N_ROWS / 32);
    transpose_kernel<<<tgrid, dim3(32, 8)>>>(x);

    iir_phase1<true><<<IIR_BLOCKS, 256>>>(bn, an);
    iir_scan<<<1, N_ROWS>>>(an, zn, 0);
    iir_phase2_fwd<<<IIR_BLOCKS, 256>>>(bn, an);

    iir_phase1<false><<<IIR_BLOCKS, 256>>>(bn, an);
    iir_scan<<<1, N_ROWS>>>(an, zn, 1);
    iir_phase2_bwd<<<IIR_BLOCKS, 256>>>(bn, an);

    comb_kernel<<<1, 320>>>(bf);

    dim3 fgrid((T_LEN + F_TILE - 1) / F_TILE, N_ROWS);
    fir_kernel<<<fgrid, F_THREADS>>>(out);
}

// round 6
// speedup vs baseline: 1.2619x; 1.2619x over previous
#include <cuda_runtime.h>

// ============================================================================
// EcgFilter — round 5: R2 coalesced-IIR pipeline + packed-f32x2 FIR.
//
// Pipeline:
//   A  : transpose x (384 x 120000) -> xT (120000 x 384)
//   B1 : IIR forward phase1  (zero-state chunk runs, transposed/coalesced)
//   B2 : IIR forward scan    (per-row affine scan over 128 chunk maps)
//   B3 : IIR forward phase2  -> yfT (ext coords, transposed)
//   B4 : IIR backward phase1 (on reversed yfT)
//   B5 : IIR backward scan
//   B6 : IIR backward phase2 -> g_mid ROW-MAJOR via per-warp smem transpose
//   C  : g = autocorr(b_fir)  (FIR filtfilt == single symmetric 301-tap conv;
//        both zi corrections provably land in the trimmed edge region)
//   D  : 301-tap conv via FFMA2 (fma.rn.f32x2) with dual-parity smem copies
// ============================================================================

#define T_LEN   120000
#define N_ROWS  384
#define EDGE    9
#define TEXT    (T_LEN + 2*EDGE)             // 120018
#define P_CH    128                          // time chunks per row
#define L_CH    938                          // ceil(TEXT / P_CH)
#define RG      (N_ROWS / 32)                // 12 row-groups of 32
#define IIR_WARPS (RG * P_CH)                // 1536
#define IIR_BLOCKS (IIR_WARPS / 8)           // 192 blocks of 256 threads

#define FIR_TAPS 151
#define G_TAPS   301
#define HALO     150
#define F_THREADS 256
#define F_RPT     8
#define F_TILE    (F_THREADS * F_RPT)        // 2048
#define F_EXT     (F_TILE + 2*HALO)          // 2348
#define F_SM      (F_EXT + 8)                // 2356

// ---------------- scratch (static __device__: allocation-free rule) --------
__device__ float g_xT [(size_t)T_LEN * N_ROWS];   // transposed input
__device__ float g_yfT[(size_t)TEXT  * N_ROWS];   // forward IIR out (ext, transposed)
__device__ float g_mid[(size_t)N_ROWS * T_LEN];   // IIR filtfilt out (row-major)
__device__ float g_V1[P_CH * N_ROWS], g_V2[P_CH * N_ROWS];
__device__ float g_Z1[P_CH * N_ROWS], g_Z2[P_CH * N_ROWS];
__device__ float g_comb[G_TAPS];

// odd extension read, row-major row pointer (used by FIR kernel)
__device__ __forceinline__ float odd_ext_load(const float* __restrict__ r, int u)
{
    if (u < 0)       return 2.0f * r[0]         - r[-u];
    if (u >= T_LEN)  return 2.0f * r[T_LEN - 1] - r[2 * T_LEN - 2 - u];
    return r[u];
}

// odd extension read in transposed layout: ext index i in [0, TEXT)
__device__ __forceinline__ float xT_ext(int i, int r)
{
    int u = i - EDGE;
    if (u < 0)
        return 2.0f * g_xT[r] - g_xT[(size_t)(-u) * N_ROWS + r];
    if (u >= T_LEN)
        return 2.0f * g_xT[(size_t)(T_LEN - 1) * N_ROWS + r]
             -        g_xT[(size_t)(2 * T_LEN - 2 - u) * N_ROWS + r];
    return g_xT[(size_t)u * N_ROWS + r];
}

// packed fp32 pair FMA: d += a * b  (FFMA2; only reachable via PTX f32x2)
__device__ __forceinline__ void ffma2(float2& d, const float2& a, const float2& b)
{
    asm("fma.rn.f32x2 %0, %1, %2, %0;"
        : "+l"(reinterpret_cast<unsigned long long&>(d))
        : "l"(reinterpret_cast<const unsigned long long&>(a)),
          "l"(reinterpret_cast<const unsigned long long&>(b)));
}

// ============================================================================
// A: transpose (row, t) -> (t, row)
// ============================================================================
__global__ __launch_bounds__(256)
void transpose_kernel(const float* __restrict__ x)
{
    __shared__ float tile[32][33];
    const int tbase = blockIdx.x * 32;
    const int rbase = blockIdx.y * 32;
    const int tx = threadIdx.x, ty = threadIdx.y;   // 32 x 8
    #pragma unroll
    for (int j = 0; j < 32; j += 8)
        tile[ty + j][tx] = x[(size_t)(rbase + ty + j) * T_LEN + tbase + tx];
    __syncthreads();
    #pragma unroll
    for (int j = 0; j < 32; j += 8)
        g_xT[(size_t)(tbase + ty + j) * N_ROWS + rbase + tx] = tile[tx][ty + j];
}

// ============================================================================
// B1/B4: phase1 — zero-state chunk run. warp = (row-group, chunk).
// ============================================================================
template<bool FWD>
__global__ __launch_bounds__(256)
void iir_phase1(const float* __restrict__ b, const float* __restrict__ a)
{
    const int w    = (blockIdx.x * 256 + threadIdx.x) >> 5;
    const int lane = threadIdx.x & 31;
    const int p    = w % P_CH;
    const int rg   = w / P_CH;
    const int r    = rg * 32 + lane;

    const float b0 = b[0], b1 = b[1], b2 = b[2];
    const float a1 = a[1], a2 = a[2];

    const int s = p * L_CH;
    int len = TEXT - s; len = len < L_CH ? len : L_CH;

    float z1 = 0.f, z2 = 0.f;
    for (int i = s; i < s + len; ++i) {
        float xn = FWD ? xT_ext(i, r)
                       : g_yfT[(size_t)(TEXT - 1 - i) * N_ROWS + r];
        float y  = fmaf(b0, xn, z1);
        float n1 = fmaf(b1, xn, z2) - a1 * y;
        float n2 = b2 * xn - a2 * y;
        z1 = n1; z2 = n2;
    }
    g_V1[p * N_ROWS + r] = z1;
    g_V2[p * N_ROWS + r] = z2;
}

// ============================================================================
// B2/B5: scan — one block, 384 threads. Threads < 128 build M_p = A^len(p),
// then every thread serially scans its row's 128 chunk maps.
// ============================================================================
__global__ __launch_bounds__(N_ROWS)
void iir_scan(const float* __restrict__ a, const float* __restrict__ zi,
              int backward)
{
    __shared__ float m00[P_CH], m01[P_CH], m10[P_CH], m11[P_CH];
    const int tid = threadIdx.x;
    const float a1 = a[1], a2 = a[2];

    if (tid < P_CH) {
        int s = tid * L_CH;
        int len = TEXT - s; len = len < L_CH ? len : L_CH;
        float c00 = -a1, c01 = 1.f, c10 = -a2, c11 = 0.f;
        float r00 = 1.f, r01 = 0.f, r10 = 0.f, r11 = 1.f;
        int e = len;
        while (e) {
            if (e & 1) {
                float t00 = r00*c00 + r01*c10, t01 = r00*c01 + r01*c11;
                float t10 = r10*c00 + r11*c10, t11 = r10*c01 + r11*c11;
                r00 = t00; r01 = t01; r10 = t10; r11 = t11;
            }
            e >>= 1;
            if (e) {
                float t00 = c00*c00 + c01*c10, t01 = c00*c01 + c01*c11;
                float t10 = c10*c00 + c11*c10, t11 = c10*c01 + c11*c11;
                c00 = t00; c01 = t01; c10 = t10; c11 = t11;
            }
        }
        m00[tid] = r00; m01[tid] = r01; m10[tid] = r10; m11[tid] = r11;
    }
    __syncthreads();

    const int r = tid;
    float e0 = backward ? g_yfT[(size_t)(TEXT - 1) * N_ROWS + r]
                        : xT_ext(0, r);
    float z1 = zi[0] * e0, z2 = zi[1] * e0;
    for (int p = 0; p < P_CH; ++p) {
        g_Z1[p * N_ROWS + r] = z1;
        g_Z2[p * N_ROWS + r] = z2;
        float v1 = g_V1[p * N_ROWS + r];
        float v2 = g_V2[p * N_ROWS + r];
        float n1 = m00[p]*z1 + m01[p]*z2 + v1;
        float n2 = m10[p]*z1 + m11[p]*z2 + v2;
        z1 = n1; z2 = n2;
    }
}

// ============================================================================
// B3: forward phase2 — rerun with correct state, emit yfT (coalesced)
// ============================================================================
__global__ __launch_bounds__(256)
void iir_phase2_fwd(const float* __restrict__ b, const float* __restrict__ a)
{
    const int w    = (blockIdx.x * 256 + threadIdx.x) >> 5;
    const int lane = threadIdx.x & 31;
    const int p    = w % P_CH;
    const int rg   = w / P_CH;
    const int r    = rg * 32 + lane;

    const float b0 = b[0], b1 = b[1], b2 = b[2];
    const float a1 = a[1], a2 = a[2];

    const int s = p * L_CH;
    int len = TEXT - s; len = len < L_CH ? len : L_CH;

    float z1 = g_Z1[p * N_ROWS + r];
    float z2 = g_Z2[p * N_ROWS + r];
    for (int i = s; i < s + len; ++i) {
        float xn = xT_ext(i, r);
        float y  = fmaf(b0, xn, z1);
        g_yfT[(size_t)i * N_ROWS + r] = y;
        float n1 = fmaf(b1, xn, z2) - a1 * y;
        float n2 = b2 * xn - a2 * y;
        z1 = n1; z2 = n2;
    }
}

// ============================================================================
// B6: backward phase2 — rerun reversed stream, write final trimmed result
// ROW-MAJOR to g_mid via per-warp 32x32 smem transpose staging.
// ============================================================================
__global__ __launch_bounds__(256)
void iir_phase2_bwd(const float* __restrict__ b, const float* __restrict__ a)
{
    __shared__ float stile[8][32][33];
    const int wib  = threadIdx.x >> 5;
    float (*sS)[33] = stile[wib];

    const int w    = (blockIdx.x * 256 + threadIdx.x) >> 5;
    const int lane = threadIdx.x & 31;
    const int p    = w % P_CH;
    const int rg   = w / P_CH;
    const int r    = rg * 32 + lane;
    const int rowbase = rg * 32;

    const float b0 = b[0], b1 = b[1], b2 = b[2];
    const float a1 = a[1], a2 = a[2];

    const int s = p * L_CH;
    int len = TEXT - s; len = len < L_CH ? len : L_CH;

    float z1 = g_Z1[p * N_ROWS + r];
    float z2 = g_Z2[p * N_ROWS + r];

    int i = s;
    while (i < s + len) {
        const int ib  = i;
        int cnt = s + len - ib; cnt = cnt < 32 ? cnt : 32;
        for (int c = 0; c < cnt; ++c, ++i) {
            float xn = g_yfT[(size_t)(TEXT - 1 - i) * N_ROWS + r];
            float y  = fmaf(b0, xn, z1);
            float n1 = fmaf(b1, xn, z2) - a1 * y;
            float n2 = b2 * xn - a2 * y;
            z1 = n1; z2 = n2;
            sS[lane][c] = y;
        }
        __syncwarp();
        const int t_ib = TEXT - 10 - ib;         // t for column 0
        const int t2 = t_ib - lane;              // column lane -> this t
        const bool ok = (lane < cnt) && (t2 >= 0) && (t2 < T_LEN);
        #pragma unroll 4
        for (int rr = 0; rr < 32; ++rr) {
            float v = sS[rr][lane];
            if (ok) g_mid[(size_t)(rowbase + rr) * T_LEN + t2] = v;
        }
        __syncwarp();
    }
}

// ============================================================================
// C: g[d] = autocorrelation of b_fir
// ============================================================================
__global__ void comb_kernel(const float* __restrict__ bf)
{
    int k = threadIdx.x;
    if (k >= G_TAPS) return;
    int d  = k - HALO;
    int j0 = d < 0 ? -d : 0;
    int j1 = d < 0 ? (FIR_TAPS - 1) : (FIR_TAPS - 1 - d);
    float acc = 0.f;
    for (int j = j0; j <= j1; ++j)
        acc = fmaf(bf[j], bf[j + d], acc);
    g_comb[k] = acc;
}

// ============================================================================
// D: 301-tap conv, packed f32x2.
//  - sT  : odd-extended tile (even-parity base),
//    sTs : same shifted by one element (odd-parity pairs are aligned LDS.64)
//  - sG2 : taps pre-duplicated {g,g}
//  - thread computes 8 outputs = 4 f32x2 accumulators
//  - dual rotating windows wE/wO (8 pairs each); 16-tap unrolled blocks keep
//    all circular indices compile-time. Taps 0..287 packed, 288..300 scalar.
// ============================================================================
__global__ __launch_bounds__(F_THREADS)
void fir_kernel(float* __restrict__ out)
{
    __shared__ __align__(16) float  sT [F_SM];
    __shared__ __align__(16) float  sTs[F_SM];
    __shared__ __align__(16) float2 sG2[G_TAPS + 1];

    const int row = blockIdx.y;
    const int t0  = blockIdx.x * F_TILE;
    const float* xr   = g_mid + (size_t)row * T_LEN;
    float*       outr = out   + (size_t)row * T_LEN;

    for (int j = threadIdx.x; j < F_EXT; j += F_THREADS)
        sT[j] = odd_ext_load(xr, t0 - HALO + j);
    for (int j = threadIdx.x; j < G_TAPS; j += F_THREADS) {
        float g = g_comb[j];
        sG2[j] = make_float2(g, g);
    }
    __syncthreads();
    for (int j = threadIdx.x; j < F_EXT - 1; j += F_THREADS)
        sTs[j] = sT[j + 1];
    __syncthreads();

    const int base = threadIdx.x * F_RPT;       // even
    float2 acc[4];
    float2 wE[8], wO[8];
    #pragma unroll
    for (int j = 0; j < 4; ++j) acc[j] = make_float2(0.f, 0.f);
    #pragma unroll
    for (int m = 0; m < 8; ++m) {               // pair index m
        wE[m] = *reinterpret_cast<const float2*>(&sT [base + 2 * m]);
        wO[m] = *reinterpret_cast<const float2*>(&sTs[base + 2 * m]);
    }

    // invariant at block start (kb2 multiple of 16, K0 = kb2/2 ≡ 0 mod 8):
    //   wE[P&7] = even pair P, wO[P&7] = odd pair P, for P in [K0, K0+7]
    #pragma unroll 1
    for (int kb2 = 0; kb2 < 288; kb2 += 16) {
        const int K0 = kb2 >> 1;
        #pragma unroll
        for (int h = 0; h < 2; ++h) {           // two 8-tap halves
            #pragma unroll
            for (int j = 0; j < 4; ++j) {
                const int k = kb2 + h * 8 + 2 * j;
                const float2 ge = sG2[k];
                const float2 go = sG2[k + 1];
                #pragma unroll
                for (int jj = 0; jj < 4; ++jj)
                    ffma2(acc[jj], ge, wE[(h * 4 + j + jj) & 7]);
                #pragma unroll
                for (int jj = 0; jj < 4; ++jj)
                    ffma2(acc[jj], go, wO[(h * 4 + j + jj) & 7]);
                // refill consumed slot with pair K0 + h*4 + 8 + j
                const int np = K0 + h * 4 + 8 + j;
                wE[(h * 4 + j) & 7] = *reinterpret_cast<const float2*>(&sT [base + 2 * np]);
                wO[(h * 4 + j) & 7] = *reinterpret_cast<const float2*>(&sTs[base + 2 * np]);
            }
        }
    }

    // tail taps 288..300 (scalar per lane)
    #pragma unroll
    for (int k = 288; k < G_TAPS; ++k) {
        const float gk = sG2[k].x;
        #pragma unroll
        for (int j = 0; j < 4; ++j) {
            acc[j].x = fmaf(gk, sT[base + k + 2 * j],     acc[j].x);
            acc[j].y = fmaf(gk, sT[base + k + 2 * j + 1], acc[j].y);
        }
    }

    const int tg = t0 + base;
    #pragma unroll
    for (int j = 0; j < 4; ++j) {
        int t = tg + 2 * j;
        if (t < T_LEN)     outr[t]     = acc[j].x;
        if (t + 1 < T_LEN) outr[t + 1] = acc[j].y;
    }
}

// ============================================================================
// Inputs (metadata order): x, b_notch(3), a_notch(3), zi_notch(2),
//                          b_fir(151), zi_fir (provably unused)
// ============================================================================
extern "C" void kernel_launch(void* const* d_in, const int* in_sizes, int n_in,
                              void* d_out, int out_size)
{
    const float* x  = (const float*)d_in[0];
    const float* bn = (const float*)d_in[1];
    const float* an = (const float*)d_in[2];
    const float* zn = (const float*)d_in[3];
    const float* bf = (const float*)d_in[4];
    float* out = (float*)d_out;

    dim3 tgrid(T_LEN / 32, N_ROWS / 32);
    transpose_kernel<<<tgrid, dim3(32, 8)>>>(x);

    iir_phase1<true><<<IIR_BLOCKS, 256>>>(bn, an);
    iir_scan<<<1, N_ROWS>>>(an, zn, 0);
    iir_phase2_fwd<<<IIR_BLOCKS, 256>>>(bn, an);

    iir_phase1<false><<<IIR_BLOCKS, 256>>>(bn, an);
    iir_scan<<<1, N_ROWS>>>(an, zn, 1);
    iir_phase2_bwd<<<IIR_BLOCKS, 256>>>(bn, an);

    comb_kernel<<<1, 320>>>(bf);

    dim3 fgrid((T_LEN + F_TILE - 1) / F_TILE, N_ROWS);
    fir_kernel<<<fgrid, F_THREADS>>>(out);
}

// round 7
// speedup vs baseline: 1.7823x; 1.4123x over previous
#include <cuda_runtime.h>

// ============================================================================
// EcgFilter — round 6: attack the measured latency/occupancy bottleneck.
//   * P_CH 128 -> 512 (6144 warps, occ 16% -> ~65%)
//   * odd extension pre-baked into g_xTe (branch-free IIR hot loops)
//   * explicit 4-wide load prefetch in every phase loop (MLP >= 4)
// Pipeline:
//   A  : transpose x -> g_xTe[EDGE..] (TEXT x 384, ext coords)
//   A2 : fill 2*EDGE extension rows of g_xTe
//   B1 : IIR fwd phase1 (zero-state chunk runs)      B2: fwd scan
//   B3 : IIR fwd phase2 -> yfT                       B4: bwd phase1
//   B5 : bwd scan                                    B6: bwd phase2 -> g_mid
//   C  : g = autocorr(b_fir) (FIR filtfilt == one symmetric 301-tap conv)
//   D  : 301-tap conv via fma.rn.f32x2 dual-parity windows
// ============================================================================

#define T_LEN   120000
#define N_ROWS  384
#define EDGE    9
#define TEXT    (T_LEN + 2*EDGE)             // 120018
#define P_CH    512                          // time chunks per row
#define L_CH    ((TEXT + P_CH - 1) / P_CH)   // 235
#define RG      (N_ROWS / 32)                // 12 row-groups of 32
#define IIR_WARPS (RG * P_CH)                // 6144
#define IIR_BLOCKS (IIR_WARPS / 8)           // 768 blocks of 256 threads

#define FIR_TAPS 151
#define G_TAPS   301
#define HALO     150
#define F_THREADS 256
#define F_RPT     8
#define F_TILE    (F_THREADS * F_RPT)        // 2048
#define F_EXT     (F_TILE + 2*HALO)          // 2348
#define F_SM      (F_EXT + 8)

// ---------------- scratch (static __device__: allocation-free rule) --------
__device__ float g_xTe[(size_t)TEXT * N_ROWS];   // odd-extended input, transposed
__device__ float g_yfT[(size_t)TEXT * N_ROWS];   // forward IIR out (ext, transposed)
__device__ float g_mid[(size_t)N_ROWS * T_LEN];  // IIR filtfilt out (row-major)
__device__ float g_V1[P_CH * N_ROWS], g_V2[P_CH * N_ROWS];
__device__ float g_Z1[P_CH * N_ROWS], g_Z2[P_CH * N_ROWS];
__device__ float g_comb[G_TAPS];

// odd extension read, row-major row pointer (FIR kernel only)
__device__ __forceinline__ float odd_ext_load(const float* __restrict__ r, int u)
{
    if (u < 0)       return 2.0f * r[0]         - r[-u];
    if (u >= T_LEN)  return 2.0f * r[T_LEN - 1] - r[2 * T_LEN - 2 - u];
    return r[u];
}

// packed fp32 pair FMA (FFMA2; PTX-only)
__device__ __forceinline__ void ffma2(float2& d, const float2& a, const float2& b)
{
    asm("fma.rn.f32x2 %0, %1, %2, %0;"
        : "+l"(reinterpret_cast<unsigned long long&>(d))
        : "l"(reinterpret_cast<const unsigned long long&>(a)),
          "l"(reinterpret_cast<const unsigned long long&>(b)));
}

// one DF2T recurrence step
__device__ __forceinline__ void iir_step(float xn, float& z1, float& z2,
                                         float b0, float b1, float b2,
                                         float a1, float a2, float& y)
{
    y = fmaf(b0, xn, z1);
    float n1 = fmaf(b1, xn, z2) - a1 * y;
    float n2 = b2 * xn - a2 * y;
    z1 = n1; z2 = n2;
}

// ============================================================================
// A: transpose (row, t) -> (t+EDGE, row) into the extended buffer
// ============================================================================
__global__ __launch_bounds__(256)
void transpose_kernel(const float* __restrict__ x)
{
    __shared__ float tile[32][33];
    const int tbase = blockIdx.x * 32;
    const int rbase = blockIdx.y * 32;
    const int tx = threadIdx.x, ty = threadIdx.y;   // 32 x 8
    #pragma unroll
    for (int j = 0; j < 32; j += 8)
        tile[ty + j][tx] = x[(size_t)(rbase + ty + j) * T_LEN + tbase + tx];
    __syncthreads();
    #pragma unroll
    for (int j = 0; j < 32; j += 8)
        g_xTe[(size_t)(tbase + ty + j + EDGE) * N_ROWS + rbase + tx] = tile[tx][ty + j];
}

// A2: fill the 2*EDGE odd-extension rows (after transpose)
__global__ __launch_bounds__(N_ROWS)
void edge_ext_kernel()
{
    const int r = threadIdx.x;
    const float x0 = g_xTe[(size_t)EDGE * N_ROWS + r];
    const float xL = g_xTe[(size_t)(T_LEN - 1 + EDGE) * N_ROWS + r];
    #pragma unroll
    for (int e = 0; e < EDGE; ++e)  // ext idx e, u = e-EDGE < 0
        g_xTe[(size_t)e * N_ROWS + r] =
            2.0f * x0 - g_xTe[(size_t)(2 * EDGE - e) * N_ROWS + r];
    #pragma unroll
    for (int e = 0; e < EDGE; ++e) {        // ext idx i = TEXT-EDGE+e
        int u = T_LEN + e;                  // u >= T_LEN
        g_xTe[(size_t)(TEXT - EDGE + e) * N_ROWS + r] =
            2.0f * xL - g_xTe[(size_t)(2 * T_LEN - 2 - u + EDGE) * N_ROWS + r];
    }
}

// ============================================================================
// B1/B4: phase1 — zero-state chunk run, branch-free, 4-wide prefetch.
// FWD: stream = g_xTe (forward).  !FWD: stream = g_yfT reversed.
// ============================================================================
template<bool FWD>
__global__ __launch_bounds__(256)
void iir_phase1(const float* __restrict__ b, const float* __restrict__ a)
{
    const int w    = (blockIdx.x * 256 + threadIdx.x) >> 5;
    const int lane = threadIdx.x & 31;
    const int p    = w % P_CH;
    const int rg   = w / P_CH;
    const int r    = rg * 32 + lane;

    const float b0 = b[0], b1 = b[1], b2 = b[2];
    const float a1 = a[1], a2 = a[2];

    const int s = p * L_CH;
    int len = TEXT - s; len = len < L_CH ? len : L_CH; len = len < 0 ? 0 : len;

    float z1 = 0.f, z2 = 0.f, y;
    int i = s;
    const int e4 = s + (len & ~3);
    for (; i < e4; i += 4) {
        float xb[4];
        #pragma unroll
        for (int u = 0; u < 4; ++u)
            xb[u] = FWD ? g_xTe[(size_t)(i + u) * N_ROWS + r]
                        : g_yfT[(size_t)(TEXT - 1 - (i + u)) * N_ROWS + r];
        #pragma unroll
        for (int u = 0; u < 4; ++u)
            iir_step(xb[u], z1, z2, b0, b1, b2, a1, a2, y);
    }
    for (; i < s + len; ++i) {
        float xn = FWD ? g_xTe[(size_t)i * N_ROWS + r]
                       : g_yfT[(size_t)(TEXT - 1 - i) * N_ROWS + r];
        iir_step(xn, z1, z2, b0, b1, b2, a1, a2, y);
    }
    g_V1[p * N_ROWS + r] = z1;
    g_V2[p * N_ROWS + r] = z2;
}

// ============================================================================
// B2/B5: scan — one block, 384 threads. First build M_p = A^len(p) for all
// 512 chunks (cooperatively), then every thread scans its row serially.
// ============================================================================
__global__ __launch_bounds__(N_ROWS)
void iir_scan(const float* __restrict__ a, const float* __restrict__ zi,
              int backward)
{
    __shared__ float m00[P_CH], m01[P_CH], m10[P_CH], m11[P_CH];
    const int tid = threadIdx.x;
    const float a1 = a[1], a2 = a[2];

    for (int p = tid; p < P_CH; p += N_ROWS) {
        int s = p * L_CH;
        int len = TEXT - s; len = len < L_CH ? len : L_CH; len = len < 0 ? 0 : len;
        float c00 = -a1, c01 = 1.f, c10 = -a2, c11 = 0.f;
        float r00 = 1.f, r01 = 0.f, r10 = 0.f, r11 = 1.f;
        int e = len;
        while (e) {
            if (e & 1) {
                float t00 = r00*c00 + r01*c10, t01 = r00*c01 + r01*c11;
                float t10 = r10*c00 + r11*c10, t11 = r10*c01 + r11*c11;
                r00 = t00; r01 = t01; r10 = t10; r11 = t11;
            }
            e >>= 1;
            if (e) {
                float t00 = c00*c00 + c01*c10, t01 = c00*c01 + c01*c11;
                float t10 = c10*c00 + c11*c10, t11 = c10*c01 + c11*c11;
                c00 = t00; c01 = t01; c10 = t10; c11 = t11;
            }
        }
        m00[p] = r00; m01[p] = r01; m10[p] = r10; m11[p] = r11;
    }
    __syncthreads();

    const int r = tid;
    float e0 = backward ? g_yfT[(size_t)(TEXT - 1) * N_ROWS + r]
                        : g_xTe[r];
    float z1 = zi[0] * e0, z2 = zi[1] * e0;
    for (int p = 0; p < P_CH; ++p) {
        g_Z1[p * N_ROWS + r] = z1;
        g_Z2[p * N_ROWS + r] = z2;
        float v1 = g_V1[p * N_ROWS + r];
        float v2 = g_V2[p * N_ROWS + r];
        float n1 = m00[p]*z1 + m01[p]*z2 + v1;
        float n2 = m10[p]*z1 + m11[p]*z2 + v2;
        z1 = n1; z2 = n2;
    }
}

// ============================================================================
// B3: forward phase2 — rerun with correct state, emit yfT, 4-wide prefetch.
// ============================================================================
__global__ __launch_bounds__(256)
void iir_phase2_fwd(const float* __restrict__ b, const float* __restrict__ a)
{
    const int w    = (blockIdx.x * 256 + threadIdx.x) >> 5;
    const int lane = threadIdx.x & 31;
    const int p    = w % P_CH;
    const int rg   = w / P_CH;
    const int r    = rg * 32 + lane;

    const float b0 = b[0], b1 = b[1], b2 = b[2];
    const float a1 = a[1], a2 = a[2];

    const int s = p * L_CH;
    int len = TEXT - s; len = len < L_CH ? len : L_CH; len = len < 0 ? 0 : len;

    float z1 = g_Z1[p * N_ROWS + r];
    float z2 = g_Z2[p * N_ROWS + r];
    float y;
    int i = s;
    const int e4 = s + (len & ~3);
    for (; i < e4; i += 4) {
        float xb[4];
        #pragma unroll
        for (int u = 0; u < 4; ++u)
            xb[u] = g_xTe[(size_t)(i + u) * N_ROWS + r];
        #pragma unroll
        for (int u = 0; u < 4; ++u) {
            iir_step(xb[u], z1, z2, b0, b1, b2, a1, a2, y);
            g_yfT[(size_t)(i + u) * N_ROWS + r] = y;
        }
    }
    for (; i < s + len; ++i) {
        iir_step(g_xTe[(size_t)i * N_ROWS + r], z1, z2, b0, b1, b2, a1, a2, y);
        g_yfT[(size_t)i * N_ROWS + r] = y;
    }
}

// ============================================================================
// B6: backward phase2 — rerun reversed stream, write final trimmed result
// ROW-MAJOR to g_mid via per-warp 32x32 smem transpose staging.
// ============================================================================
__global__ __launch_bounds__(256)
void iir_phase2_bwd(const float* __restrict__ b, const float* __restrict__ a)
{
    __shared__ float stile[8][32][33];
    const int wib  = threadIdx.x >> 5;
    float (*sS)[33] = stile[wib];

    const int w    = (blockIdx.x * 256 + threadIdx.x) >> 5;
    const int lane = threadIdx.x & 31;
    const int p    = w % P_CH;
    const int rg   = w / P_CH;
    const int r    = rg * 32 + lane;
    const int rowbase = rg * 32;

    const float b0 = b[0], b1 = b[1], b2 = b[2];
    const float a1 = a[1], a2 = a[2];

    const int s = p * L_CH;
    int len = TEXT - s; len = len < L_CH ? len : L_CH; len = len < 0 ? 0 : len;

    float z1 = g_Z1[p * N_ROWS + r];
    float z2 = g_Z2[p * N_ROWS + r];
    float y;

    int i = s;
    while (i < s + len) {
        const int ib  = i;
        int cnt = s + len - ib; cnt = cnt < 32 ? cnt : 32;
        if (cnt == 32) {
            #pragma unroll 1
            for (int c = 0; c < 32; c += 4) {
                float xb[4];
                #pragma unroll
                for (int u = 0; u < 4; ++u)
                    xb[u] = g_yfT[(size_t)(TEXT - 1 - (i + u)) * N_ROWS + r];
                #pragma unroll
                for (int u = 0; u < 4; ++u) {
                    iir_step(xb[u], z1, z2, b0, b1, b2, a1, a2, y);
                    sS[lane][c + u] = y;
                }
                i += 4;
            }
        } else {
            for (int c = 0; c < cnt; ++c, ++i) {
                iir_step(g_yfT[(size_t)(TEXT - 1 - i) * N_ROWS + r],
                         z1, z2, b0, b1, b2, a1, a2, y);
                sS[lane][c] = y;
            }
        }
        __syncwarp();
        const int t_ib = TEXT - 10 - ib;         // final t for column 0
        const int t2 = t_ib - lane;              // column lane -> this t
        const bool ok = (lane < cnt) && (t2 >= 0) && (t2 < T_LEN);
        #pragma unroll 4
        for (int rr = 0; rr < 32; ++rr) {
            float v = sS[rr][lane];
            if (ok) g_mid[(size_t)(rowbase + rr) * T_LEN + t2] = v;
        }
        __syncwarp();
    }
}

// ============================================================================
// C: g[d] = autocorrelation of b_fir
// ============================================================================
__global__ void comb_kernel(const float* __restrict__ bf)
{
    int k = threadIdx.x;
    if (k >= G_TAPS) return;
    int d  = k - HALO;
    int j0 = d < 0 ? -d : 0;
    int j1 = d < 0 ? (FIR_TAPS - 1) : (FIR_TAPS - 1 - d);
    float acc = 0.f;
    for (int j = j0; j <= j1; ++j)
        acc = fmaf(bf[j], bf[j + d], acc);
    g_comb[k] = acc;
}

// ============================================================================
// D: 301-tap conv, packed f32x2 with dual-parity smem copies (unchanged)
// ============================================================================
__global__ __launch_bounds__(F_THREADS)
void fir_kernel(float* __restrict__ out)
{
    __shared__ __align__(16) float  sT [F_SM];
    __shared__ __align__(16) float  sTs[F_SM];
    __shared__ __align__(16) float2 sG2[G_TAPS + 1];

    const int row = blockIdx.y;
    const int t0  = blockIdx.x * F_TILE;
    const float* xr   = g_mid + (size_t)row * T_LEN;
    float*       outr = out   + (size_t)row * T_LEN;

    for (int j = threadIdx.x; j < F_EXT; j += F_THREADS)
        sT[j] = odd_ext_load(xr, t0 - HALO + j);
    for (int j = threadIdx.x; j < G_TAPS; j += F_THREADS) {
        float g = g_comb[j];
        sG2[j] = make_float2(g, g);
    }
    __syncthreads();
    for (int j = threadIdx.x; j < F_EXT - 1; j += F_THREADS)
        sTs[j] = sT[j + 1];
    __syncthreads();

    const int base = threadIdx.x * F_RPT;       // even
    float2 acc[4];
    float2 wE[8], wO[8];
    #pragma unroll
    for (int j = 0; j < 4; ++j) acc[j] = make_float2(0.f, 0.f);
    #pragma unroll
    for (int m = 0; m < 8; ++m) {
        wE[m] = *reinterpret_cast<const float2*>(&sT [base + 2 * m]);
        wO[m] = *reinterpret_cast<const float2*>(&sTs[base + 2 * m]);
    }

    #pragma unroll 1
    for (int kb2 = 0; kb2 < 288; kb2 += 16) {
        const int K0 = kb2 >> 1;
        #pragma unroll
        for (int h = 0; h < 2; ++h) {
            #pragma unroll
            for (int j = 0; j < 4; ++j) {
                const int k = kb2 + h * 8 + 2 * j;
                const float2 ge = sG2[k];
                const float2 go = sG2[k + 1];
                #pragma unroll
                for (int jj = 0; jj < 4; ++jj)
                    ffma2(acc[jj], ge, wE[(h * 4 + j + jj) & 7]);
                #pragma unroll
                for (int jj = 0; jj < 4; ++jj)
                    ffma2(acc[jj], go, wO[(h * 4 + j + jj) & 7]);
                const int np = K0 + h * 4 + 8 + j;
                wE[(h * 4 + j) & 7] = *reinterpret_cast<const float2*>(&sT [base + 2 * np]);
                wO[(h * 4 + j) & 7] = *reinterpret_cast<const float2*>(&sTs[base + 2 * np]);
            }
        }
    }

    #pragma unroll
    for (int k = 288; k < G_TAPS; ++k) {
        const float gk = sG2[k].x;
        #pragma unroll
        for (int j = 0; j < 4; ++j) {
            acc[j].x = fmaf(gk, sT[base + k + 2 * j],     acc[j].x);
            acc[j].y = fmaf(gk, sT[base + k + 2 * j + 1], acc[j].y);
        }
    }

    const int tg = t0 + base;
    #pragma unroll
    for (int j = 0; j < 4; ++j) {
        int t = tg + 2 * j;
        if (t < T_LEN)     outr[t]     = acc[j].x;
        if (t + 1 < T_LEN) outr[t + 1] = acc[j].y;
    }
}

// ============================================================================
// Inputs (metadata order): x, b_notch(3), a_notch(3), zi_notch(2),
//                          b_fir(151), zi_fir (provably unused)
// ============================================================================
extern "C" void kernel_launch(void* const* d_in, const int* in_sizes, int n_in,
                              void* d_out, int out_size)
{
    const float* x  = (const float*)d_in[0];
    const float* bn = (const float*)d_in[1];
    const float* an = (const float*)d_in[2];
    const float* zn = (const float*)d_in[3];
    const float* bf = (const float*)d_in[4];
    float* out = (float*)d_out;

    dim3 tgrid(T_LEN / 32, N_ROWS / 32);
    transpose_kernel<<<tgrid, dim3(32, 8)>>>(x);
    edge_ext_kernel<<<1, N_ROWS>>>();

    iir_phase1<true><<<IIR_BLOCKS, 256>>>(bn, an);
    iir_scan<<<1, N_ROWS>>>(an, zn, 0);
    iir_phase2_fwd<<<IIR_BLOCKS, 256>>>(bn, an);

    iir_phase1<false><<<IIR_BLOCKS, 256>>>(bn, an);
    iir_scan<<<1, N_ROWS>>>(an, zn, 1);
    iir_phase2_bwd<<<IIR_BLOCKS, 256>>>(bn, an);

    comb_kernel<<<1, 320>>>(bf);

    dim3 fgrid((T_LEN + F_TILE - 1) / F_TILE, N_ROWS);
    fir_kernel<<<fgrid, F_THREADS>>>(out);
}

// round 10
// speedup vs baseline: 2.1316x; 1.1960x over previous
#include <cuda_runtime.h>

// ============================================================================
// EcgFilter — round 9: resubmit R8 (parallel scan + phase fusion), cleaned.
//   * serial grid=1 scan (2 x 256us measured in R7 profile) -> Kogge-Stone
//     over affine maps, one block per row (384 blocks x 512 threads, 9 steps).
//   * backward pass re-based on PHYSICAL chunks processed high->low, so the
//     forward-phase2 kernel also computes backward zero-state maps in the
//     same pass (saves a full 184MB yfT read + one launch).
// Pipeline:
//   A  : transpose x -> g_xTe[EDGE..] (TEXT x 384, ext coords)
//   A2 : fill 2*EDGE extension rows of g_xTe
//   B1 : fwd phase1 (zero-state chunk runs)
//   B2 : fwd parallel scan
//   B3 : FUSED fwd phase2 (emit yfT) + bwd phase1 (zero-state maps)
//   B4 : bwd parallel scan (physical chunks, descending order)
//   B5 : bwd phase2 -> g_mid row-major (t = i - EDGE), smem transpose staging
//   C  : g = autocorr(b_fir)   (FIR filtfilt == one symmetric 301-tap conv)
//   D  : 301-tap conv via fma.rn.f32x2 dual-parity windows
// ============================================================================

#define T_LEN   120000
#define N_ROWS  384
#define EDGE    9
#define TEXT    (T_LEN + 2*EDGE)             // 120018
#define P_CH    512                          // physical time chunks per row
#define L_CH    ((TEXT + P_CH - 1) / P_CH)   // 235
#define RG      (N_ROWS / 32)                // 12 row-groups of 32
#define IIR_WARPS (RG * P_CH)                // 6144
#define IIR_BLOCKS (IIR_WARPS / 8)           // 768 blocks of 256 threads

#define FIR_TAPS 151
#define G_TAPS   301
#define HALO     150
#define F_THREADS 256
#define F_RPT     8
#define F_TILE    (F_THREADS * F_RPT)        // 2048
#define F_EXT     (F_TILE + 2*HALO)          // 2348
#define F_SM      (F_EXT + 8)

// ---------------- scratch (static __device__: allocation-free rule) --------
__device__ float g_xTe[(size_t)TEXT * N_ROWS];   // odd-extended input, transposed
__device__ float g_yfT[(size_t)TEXT * N_ROWS];   // forward IIR out (ext, transposed)
__device__ float g_mid[(size_t)N_ROWS * T_LEN];  // IIR filtfilt out (row-major)
__device__ float g_V1[P_CH * N_ROWS], g_V2[P_CH * N_ROWS];  // by PHYSICAL chunk
__device__ float g_Z1[P_CH * N_ROWS], g_Z2[P_CH * N_ROWS];  // by PHYSICAL chunk
__device__ float g_comb[G_TAPS];

// chunk extent (physical chunk start s): clamped length
__device__ __forceinline__ int chunk_len(int s)
{
    int len = TEXT - s;
    len = len < L_CH ? len : L_CH;
    return len < 0 ? 0 : len;
}

// odd extension read, row-major row pointer (FIR kernel only)
__device__ __forceinline__ float odd_ext_load(const float* __restrict__ r, int u)
{
    if (u < 0)       return 2.0f * r[0]         - r[-u];
    if (u >= T_LEN)  return 2.0f * r[T_LEN - 1] - r[2 * T_LEN - 2 - u];
    return r[u];
}

// packed fp32 pair FMA (FFMA2; PTX-only)
__device__ __forceinline__ void ffma2(float2& d, const float2& a, const float2& b)
{
    asm("fma.rn.f32x2 %0, %1, %2, %0;"
        : "+l"(reinterpret_cast<unsigned long long&>(d))
        : "l"(reinterpret_cast<const unsigned long long&>(a)),
          "l"(reinterpret_cast<const unsigned long long&>(b)));
}

// one DF2T recurrence step
__device__ __forceinline__ void iir_step(float xn, float& z1, float& z2,
                                         float b0, float b1, float b2,
                                         float a1, float a2, float& y)
{
    y = fmaf(b0, xn, z1);
    float n1 = fmaf(b1, xn, z2) - a1 * y;
    float n2 = b2 * xn - a2 * y;
    z1 = n1; z2 = n2;
}

// M = A^n for A = [[-a1, 1], [-a2, 0]] (powers of A commute)
__device__ __forceinline__ void a_pow(int n, float a1, float a2,
                                      float& m00, float& m01, float& m10, float& m11)
{
    float c00 = -a1, c01 = 1.f, c10 = -a2, c11 = 0.f;
    float r00 = 1.f, r01 = 0.f, r10 = 0.f, r11 = 1.f;
    int e = n;
    while (e) {
        if (e & 1) {
            float t00 = r00*c00 + r01*c10, t01 = r00*c01 + r01*c11;
            float t10 = r10*c00 + r11*c10, t11 = r10*c01 + r11*c11;
            r00 = t00; r01 = t01; r10 = t10; r11 = t11;
        }
        e >>= 1;
        if (e) {
            float t00 = c00*c00 + c01*c10, t01 = c00*c01 + c01*c11;
            float t10 = c10*c00 + c11*c10, t11 = c10*c01 + c11*c11;
            c00 = t00; c01 = t01; c10 = t10; c11 = t11;
        }
    }
    m00 = r00; m01 = r01; m10 = r10; m11 = r11;
}

// ============================================================================
// A: transpose (row, t) -> (t+EDGE, row) into the extended buffer
// ============================================================================
__global__ __launch_bounds__(256)
void transpose_kernel(const float* __restrict__ x)
{
    __shared__ float tile[32][33];
    const int tbase = blockIdx.x * 32;
    const int rbase = blockIdx.y * 32;
    const int tx = threadIdx.x, ty = threadIdx.y;   // 32 x 8
    #pragma unroll
    for (int j = 0; j < 32; j += 8)
        tile[ty + j][tx] = x[(size_t)(rbase + ty + j) * T_LEN + tbase + tx];
    __syncthreads();
    #pragma unroll
    for (int j = 0; j < 32; j += 8)
        g_xTe[(size_t)(tbase + ty + j + EDGE) * N_ROWS + rbase + tx] = tile[tx][ty + j];
}

// A2: fill the 2*EDGE odd-extension rows (after transpose)
__global__ __launch_bounds__(N_ROWS)
void edge_ext_kernel()
{
    const int r = threadIdx.x;
    const float x0 = g_xTe[(size_t)EDGE * N_ROWS + r];
    const float xL = g_xTe[(size_t)(T_LEN - 1 + EDGE) * N_ROWS + r];
    #pragma unroll
    for (int e = 0; e < EDGE; ++e)
        g_xTe[(size_t)e * N_ROWS + r] =
            2.0f * x0 - g_xTe[(size_t)(2 * EDGE - e) * N_ROWS + r];
    #pragma unroll
    for (int e = 0; e < EDGE; ++e) {
        int u = T_LEN + e;
        g_xTe[(size_t)(TEXT - EDGE + e) * N_ROWS + r] =
            2.0f * xL - g_xTe[(size_t)(2 * T_LEN - 2 - u + EDGE) * N_ROWS + r];
    }
}

// ============================================================================
// B1: forward phase1 — zero-state chunk run, 4-wide prefetch.
// ============================================================================
__global__ __launch_bounds__(256)
void iir_phase1_fwd(const float* __restrict__ b, const float* __restrict__ a)
{
    const int w    = (blockIdx.x * 256 + threadIdx.x) >> 5;
    const int lane = threadIdx.x & 31;
    const int p    = w % P_CH;
    const int rg   = w / P_CH;
    const int r    = rg * 32 + lane;

    const float b0 = b[0], b1 = b[1], b2 = b[2];
    const float a1 = a[1], a2 = a[2];

    const int s = p * L_CH;
    const int len = chunk_len(s);

    float z1 = 0.f, z2 = 0.f, y;
    int i = s;
    const int e4 = s + (len & ~3);
    for (; i < e4; i += 4) {
        float xb[4];
        #pragma unroll
        for (int u = 0; u < 4; ++u)
            xb[u] = g_xTe[(size_t)(i + u) * N_ROWS + r];
        #pragma unroll
        for (int u = 0; u < 4; ++u)
            iir_step(xb[u], z1, z2, b0, b1, b2, a1, a2, y);
    }
    for (; i < s + len; ++i)
        iir_step(g_xTe[(size_t)i * N_ROWS + r], z1, z2, b0, b1, b2, a1, a2, y);

    g_V1[p * N_ROWS + r] = z1;
    g_V2[p * N_ROWS + r] = z2;
}

// ============================================================================
// B2/B4: PARALLEL scan — one block per row, 512 threads = 512 scan positions.
// Forward: scan position q = physical chunk q (ascending).
// Backward: scan position q = physical chunk P_CH-1-q (descending physical).
// Kogge-Stone inclusive scan over affine maps; thread q applies its EXCLUSIVE
// prefix to z_init and stores the state entering its PHYSICAL chunk.
// Composition (older map first): (M,v) = (Mp*Mq, Mp*vq + vp).
// ============================================================================
__global__ __launch_bounds__(P_CH)
void iir_scan_par(const float* __restrict__ a, const float* __restrict__ zi,
                  int backward)
{
    __shared__ float sm00[P_CH], sm01[P_CH], sm10[P_CH], sm11[P_CH];
    __shared__ float sv1 [P_CH], sv2 [P_CH];

    const int row = blockIdx.x;
    const int q   = threadIdx.x;                       // scan position
    const int c   = backward ? (P_CH - 1 - q) : q;     // physical chunk
    const float a1 = a[1], a2 = a[2];

    float m00, m01, m10, m11;
    a_pow(chunk_len(c * L_CH), a1, a2, m00, m01, m10, m11);
    float v1 = g_V1[c * N_ROWS + row];
    float v2 = g_V2[c * N_ROWS + row];

    sm00[q] = m00; sm01[q] = m01; sm10[q] = m10; sm11[q] = m11;
    sv1[q] = v1;   sv2[q] = v2;
    __syncthreads();

    #pragma unroll
    for (int d = 1; d < P_CH; d <<= 1) {
        float q00 = 0.f, q01 = 0.f, q10 = 0.f, q11 = 0.f, qv1 = 0.f, qv2 = 0.f;
        if (q >= d) {
            q00 = sm00[q - d]; q01 = sm01[q - d];
            q10 = sm10[q - d]; q11 = sm11[q - d];
            qv1 = sv1[q - d];  qv2 = sv2[q - d];
        }
        __syncthreads();
        if (q >= d) {
            float n00 = m00*q00 + m01*q10, n01 = m00*q01 + m01*q11;
            float n10 = m10*q00 + m11*q10, n11 = m10*q01 + m11*q11;
            float nv1 = m00*qv1 + m01*qv2 + v1;
            float nv2 = m10*qv1 + m11*qv2 + v2;
            m00 = n00; m01 = n01; m10 = n10; m11 = n11; v1 = nv1; v2 = nv2;
            sm00[q] = m00; sm01[q] = m01; sm10[q] = m10; sm11[q] = m11;
            sv1[q] = v1;   sv2[q] = v2;
        }
        __syncthreads();
    }

    // z_init = zi * (first sample of the stream)
    float e0 = backward ? g_yfT[(size_t)(TEXT - 1) * N_ROWS + row]
                        : g_xTe[row];
    float zi1 = zi[0] * e0, zi2 = zi[1] * e0;
    float z1, z2;
    if (q == 0) { z1 = zi1; z2 = zi2; }
    else {
        float p00 = sm00[q-1], p01 = sm01[q-1], p10 = sm10[q-1], p11 = sm11[q-1];
        z1 = p00*zi1 + p01*zi2 + sv1[q-1];
        z2 = p10*zi1 + p11*zi2 + sv2[q-1];
    }
    g_Z1[c * N_ROWS + row] = z1;
    g_Z2[c * N_ROWS + row] = z2;
}

// ============================================================================
// B3: FUSED forward phase2 + backward phase1.
//  1) corrected forward recursion over the chunk, write yfT
//  2) backward zero-state recursion over the SAME chunk in reverse
//     (backward pass == same samples visited in descending physical order).
//     Re-reads are this thread's own just-written values: per-thread ordered,
//     serviced from L1/L2.
// ============================================================================
__global__ __launch_bounds__(256)
void iir_mid(const float* __restrict__ b, const float* __restrict__ a)
{
    const int w    = (blockIdx.x * 256 + threadIdx.x) >> 5;
    const int lane = threadIdx.x & 31;
    const int p    = w % P_CH;
    const int rg   = w / P_CH;
    const int r    = rg * 32 + lane;

    const float b0 = b[0], b1 = b[1], b2 = b[2];
    const float a1 = a[1], a2 = a[2];

    const int s = p * L_CH;
    const int len = chunk_len(s);

    // forward phase2
    float z1 = g_Z1[p * N_ROWS + r];
    float z2 = g_Z2[p * N_ROWS + r];
    float y;
    int i = s;
    const int e4 = s + (len & ~3);
    for (; i < e4; i += 4) {
        float xb[4];
        #pragma unroll
        for (int u = 0; u < 4; ++u)
            xb[u] = g_xTe[(size_t)(i + u) * N_ROWS + r];
        #pragma unroll
        for (int u = 0; u < 4; ++u) {
            iir_step(xb[u], z1, z2, b0, b1, b2, a1, a2, y);
            g_yfT[(size_t)(i + u) * N_ROWS + r] = y;
        }
    }
    for (; i < s + len; ++i) {
        iir_step(g_xTe[(size_t)i * N_ROWS + r], z1, z2, b0, b1, b2, a1, a2, y);
        g_yfT[(size_t)i * N_ROWS + r] = y;
    }

    // backward phase1: zero-state run over the SAME chunk, descending.
    float bz1 = 0.f, bz2 = 0.f;
    int j = s + len - 1;
    const int cnt4 = len & ~3;
    for (int c = 0; c < cnt4; c += 4, j -= 4) {
        float xb[4];
        #pragma unroll
        for (int u = 0; u < 4; ++u)
            xb[u] = g_yfT[(size_t)(j - u) * N_ROWS + r];
        #pragma unroll
        for (int u = 0; u < 4; ++u)
            iir_step(xb[u], bz1, bz2, b0, b1, b2, a1, a2, y);
    }
    for (; j >= s; --j)
        iir_step(g_yfT[(size_t)j * N_ROWS + r], bz1, bz2, b0, b1, b2, a1, a2, y);

    g_V1[p * N_ROWS + r] = bz1;
    g_V2[p * N_ROWS + r] = bz2;
}

// ============================================================================
// B5: backward phase2 — physical chunk p processed descending; output
// index t = i - EDGE; row-major writes via per-warp 32x32 smem staging.
// ============================================================================
__global__ __launch_bounds__(256)
void iir_phase2_bwd(const float* __restrict__ b, const float* __restrict__ a)
{
    __shared__ float stile[8][32][33];
    const int wib  = threadIdx.x >> 5;
    float (*sS)[33] = stile[wib];

    const int w    = (blockIdx.x * 256 + threadIdx.x) >> 5;
    const int lane = threadIdx.x & 31;
    const int p    = w % P_CH;
    const int rg   = w / P_CH;
    const int r    = rg * 32 + lane;
    const int rowbase = rg * 32;

    const float b0 = b[0], b1 = b[1], b2 = b[2];
    const float a1 = a[1], a2 = a[2];

    const int s = p * L_CH;
    const int len = chunk_len(s);

    float z1 = g_Z1[p * N_ROWS + r];
    float z2 = g_Z2[p * N_ROWS + r];
    float y;

    int i = s + len - 1;                     // descending physical index
    int remaining = len;
    while (remaining > 0) {
        const int itop = i;
        int cnt = remaining < 32 ? remaining : 32;
        if (cnt == 32) {
            #pragma unroll 1
            for (int c = 0; c < 32; c += 4) {
                float xb[4];
                #pragma unroll
                for (int u = 0; u < 4; ++u)
                    xb[u] = g_yfT[(size_t)(i - u) * N_ROWS + r];
                #pragma unroll
                for (int u = 0; u < 4; ++u) {
                    iir_step(xb[u], z1, z2, b0, b1, b2, a1, a2, y);
                    sS[lane][c + u] = y;
                }
                i -= 4;
            }
        } else {
            for (int c = 0; c < cnt; ++c, --i) {
                iir_step(g_yfT[(size_t)i * N_ROWS + r],
                         z1, z2, b0, b1, b2, a1, a2, y);
                sS[lane][c] = y;
            }
        }
        remaining -= cnt;
        __syncwarp();
        // column c holds time t = itop - c - EDGE for each staged row
        const int ttop = itop - EDGE;
        const int t2 = ttop - lane;
        const bool ok = (lane < cnt) && (t2 >= 0) && (t2 < T_LEN);
        #pragma unroll 4
        for (int rr = 0; rr < 32; ++rr) {
            float v = sS[rr][lane];
            if (ok) g_mid[(size_t)(rowbase + rr) * T_LEN + t2] = v;
        }
        __syncwarp();
    }
}

// ============================================================================
// C: g[d] = autocorrelation of b_fir
// ============================================================================
__global__ void comb_kernel(const float* __restrict__ bf)
{
    int k = threadIdx.x;
    if (k >= G_TAPS) return;
    int d  = k - HALO;
    int j0 = d < 0 ? -d : 0;
    int j1 = d < 0 ? (FIR_TAPS - 1) : (FIR_TAPS - 1 - d);
    float acc = 0.f;
    for (int j = j0; j <= j1; ++j)
        acc = fmaf(bf[j], bf[j + d], acc);
    g_comb[k] = acc;
}

// ============================================================================
// D: 301-tap conv, packed f32x2 with dual-parity smem copies
// ============================================================================
__global__ __launch_bounds__(F_THREADS)
void fir_kernel(float* __restrict__ out)
{
    __shared__ __align__(16) float  sT [F_SM];
    __shared__ __align__(16) float  sTs[F_SM];
    __shared__ __align__(16) float2 sG2[G_TAPS + 1];

    const int row = blockIdx.y;
    const int t0  = blockIdx.x * F_TILE;
    const float* xr   = g_mid + (size_t)row * T_LEN;
    float*       outr = out   + (size_t)row * T_LEN;

    for (int j = threadIdx.x; j < F_EXT; j += F_THREADS)
        sT[j] = odd_ext_load(xr, t0 - HALO + j);
    for (int j = threadIdx.x; j < G_TAPS; j += F_THREADS) {
        float g = g_comb[j];
        sG2[j] = make_float2(g, g);
    }
    __syncthreads();
    for (int j = threadIdx.x; j < F_EXT - 1; j += F_THREADS)
        sTs[j] = sT[j + 1];
    __syncthreads();

    const int base = threadIdx.x * F_RPT;       // even
    float2 acc[4];
    float2 wE[8], wO[8];
    #pragma unroll
    for (int j = 0; j < 4; ++j) acc[j] = make_float2(0.f, 0.f);
    #pragma unroll
    for (int m = 0; m < 8; ++m) {
        wE[m] = *reinterpret_cast<const float2*>(&sT [base + 2 * m]);
        wO[m] = *reinterpret_cast<const float2*>(&sTs[base + 2 * m]);
    }

    #pragma unroll 1
    for (int kb2 = 0; kb2 < 288; kb2 += 16) {
        const int K0 = kb2 >> 1;
        #pragma unroll
        for (int h = 0; h < 2; ++h) {
            #pragma unroll
            for (int j = 0; j < 4; ++j) {
                const int k = kb2 + h * 8 + 2 * j;
                const float2 ge = sG2[k];
                const float2 go = sG2[k + 1];
                #pragma unroll
                for (int jj = 0; jj < 4; ++jj)
                    ffma2(acc[jj], ge, wE[(h * 4 + j + jj) & 7]);
                #pragma unroll
                for (int jj = 0; jj < 4; ++jj)
                    ffma2(acc[jj], go, wO[(h * 4 + j + jj) & 7]);
                const int np = K0 + h * 4 + 8 + j;
                wE[(h * 4 + j) & 7] = *reinterpret_cast<const float2*>(&sT [base + 2 * np]);
                wO[(h * 4 + j) & 7] = *reinterpret_cast<const float2*>(&sTs[base + 2 * np]);
            }
        }
    }

    #pragma unroll
    for (int k = 288; k < G_TAPS; ++k) {
        const float gk = sG2[k].x;
        #pragma unroll
        for (int j = 0; j < 4; ++j) {
            acc[j].x = fmaf(gk, sT[base + k + 2 * j],     acc[j].x);
            acc[j].y = fmaf(gk, sT[base + k + 2 * j + 1], acc[j].y);
        }
    }

    const int tg = t0 + base;
    #pragma unroll
    for (int j = 0; j < 4; ++j) {
        int t = tg + 2 * j;
        if (t < T_LEN)     outr[t]     = acc[j].x;
        if (t + 1 < T_LEN) outr[t + 1] = acc[j].y;
    }
}

// ============================================================================
// Inputs (metadata order): x, b_notch(3), a_notch(3), zi_notch(2),
//                          b_fir(151), zi_fir (provably unused)
// ============================================================================
extern "C" void kernel_launch(void* const* d_in, const int* in_sizes, int n_in,
                              void* d_out, int out_size)
{
    const float* x  = (const float*)d_in[0];
    const float* bn = (const float*)d_in[1];
    const float* an = (const float*)d_in[2];
    const float* zn = (const float*)d_in[3];
    const float* bf = (const float*)d_in[4];
    float* out = (float*)d_out;

    dim3 tgrid(T_LEN / 32, N_ROWS / 32);
    transpose_kernel<<<tgrid, dim3(32, 8)>>>(x);
    edge_ext_kernel<<<1, N_ROWS>>>();

    iir_phase1_fwd<<<IIR_BLOCKS, 256>>>(bn, an);
    iir_scan_par<<<N_ROWS, P_CH>>>(an, zn, 0);
    iir_mid<<<IIR_BLOCKS, 256>>>(bn, an);        // fwd phase2 + bwd phase1
    iir_scan_par<<<N_ROWS, P_CH>>>(an, zn, 1);
    iir_phase2_bwd<<<IIR_BLOCKS, 256>>>(bn, an);

    comb_kernel<<<1, 320>>>(bf);

    dim3 fgrid((T_LEN + F_TILE - 1) / F_TILE, N_ROWS);
    fir_kernel<<<fgrid, F_THREADS>>>(out);
}

// round 11
// speedup vs baseline: 2.1407x; 1.0043x over previous
#include <cuda_runtime.h>

// ============================================================================
// EcgFilter — round 10: profile-visibility reorder + deeper prefetch.
//   * comb_kernel launched FIRST -> ncu's "-s 5" now lands on iir_mid
//     (heaviest IIR kernel) instead of the 13us scan.
//   * 8-wide load prefetch (was 4) in all IIR recurrence loops.
// Pipeline (launch order):
//   0 C  : g = autocorr(b_fir)   (independent; FIR filtfilt == one 301-tap conv)
//   1 A  : transpose x -> g_xTe[EDGE..] (TEXT x 384, ext coords)
//   2 A2 : fill 2*EDGE extension rows of g_xTe
//   3 B1 : fwd phase1 (zero-state chunk runs)
//   4 B2 : fwd parallel scan (Kogge-Stone over affine maps)
//   5 B3 : FUSED fwd phase2 (emit yfT) + bwd phase1 (zero-state maps) [profiled]
//   6 B4 : bwd parallel scan (physical chunks, descending order)
//   7 B5 : bwd phase2 -> g_mid row-major, smem transpose staging
//   8 D  : 301-tap conv via fma.rn.f32x2 dual-parity windows
// ============================================================================

#define T_LEN   120000
#define N_ROWS  384
#define EDGE    9
#define TEXT    (T_LEN + 2*EDGE)             // 120018
#define P_CH    512                          // physical time chunks per row
#define L_CH    ((TEXT + P_CH - 1) / P_CH)   // 235
#define RG      (N_ROWS / 32)                // 12 row-groups of 32
#define IIR_WARPS (RG * P_CH)                // 6144
#define IIR_BLOCKS (IIR_WARPS / 8)           // 768 blocks of 256 threads

#define FIR_TAPS 151
#define G_TAPS   301
#define HALO     150
#define F_THREADS 256
#define F_RPT     8
#define F_TILE    (F_THREADS * F_RPT)        // 2048
#define F_EXT     (F_TILE + 2*HALO)          // 2348
#define F_SM      (F_EXT + 8)

// ---------------- scratch (static __device__: allocation-free rule) --------
__device__ float g_xTe[(size_t)TEXT * N_ROWS];   // odd-extended input, transposed
__device__ float g_yfT[(size_t)TEXT * N_ROWS];   // forward IIR out (ext, transposed)
__device__ float g_mid[(size_t)N_ROWS * T_LEN];  // IIR filtfilt out (row-major)
__device__ float g_V1[P_CH * N_ROWS], g_V2[P_CH * N_ROWS];  // by PHYSICAL chunk
__device__ float g_Z1[P_CH * N_ROWS], g_Z2[P_CH * N_ROWS];  // by PHYSICAL chunk
__device__ float g_comb[G_TAPS];

// chunk extent (physical chunk start s): clamped length
__device__ __forceinline__ int chunk_len(int s)
{
    int len = TEXT - s;
    len = len < L_CH ? len : L_CH;
    return len < 0 ? 0 : len;
}

// odd extension read, row-major row pointer (FIR kernel only)
__device__ __forceinline__ float odd_ext_load(const float* __restrict__ r, int u)
{
    if (u < 0)       return 2.0f * r[0]         - r[-u];
    if (u >= T_LEN)  return 2.0f * r[T_LEN - 1] - r[2 * T_LEN - 2 - u];
    return r[u];
}

// packed fp32 pair FMA (FFMA2; PTX-only)
__device__ __forceinline__ void ffma2(float2& d, const float2& a, const float2& b)
{
    asm("fma.rn.f32x2 %0, %1, %2, %0;"
        : "+l"(reinterpret_cast<unsigned long long&>(d))
        : "l"(reinterpret_cast<const unsigned long long&>(a)),
          "l"(reinterpret_cast<const unsigned long long&>(b)));
}

// one DF2T recurrence step
__device__ __forceinline__ void iir_step(float xn, float& z1, float& z2,
                                         float b0, float b1, float b2,
                                         float a1, float a2, float& y)
{
    y = fmaf(b0, xn, z1);
    float n1 = fmaf(b1, xn, z2) - a1 * y;
    float n2 = b2 * xn - a2 * y;
    z1 = n1; z2 = n2;
}

// M = A^n for A = [[-a1, 1], [-a2, 0]] (powers of A commute)
__device__ __forceinline__ void a_pow(int n, float a1, float a2,
                                      float& m00, float& m01, float& m10, float& m11)
{
    float c00 = -a1, c01 = 1.f, c10 = -a2, c11 = 0.f;
    float r00 = 1.f, r01 = 0.f, r10 = 0.f, r11 = 1.f;
    int e = n;
    while (e) {
        if (e & 1) {
            float t00 = r00*c00 + r01*c10, t01 = r00*c01 + r01*c11;
            float t10 = r10*c00 + r11*c10, t11 = r10*c01 + r11*c11;
            r00 = t00; r01 = t01; r10 = t10; r11 = t11;
        }
        e >>= 1;
        if (e) {
            float t00 = c00*c00 + c01*c10, t01 = c00*c01 + c01*c11;
            float t10 = c10*c00 + c11*c10, t11 = c10*c01 + c11*c11;
            c00 = t00; c01 = t01; c10 = t10; c11 = t11;
        }
    }
    m00 = r00; m01 = r01; m10 = r10; m11 = r11;
}

// ============================================================================
// C: g[d] = autocorrelation of b_fir  (launched FIRST — independent)
// ============================================================================
__global__ void comb_kernel(const float* __restrict__ bf)
{
    int k = threadIdx.x;
    if (k >= G_TAPS) return;
    int d  = k - HALO;
    int j0 = d < 0 ? -d : 0;
    int j1 = d < 0 ? (FIR_TAPS - 1) : (FIR_TAPS - 1 - d);
    float acc = 0.f;
    for (int j = j0; j <= j1; ++j)
        acc = fmaf(bf[j], bf[j + d], acc);
    g_comb[k] = acc;
}

// ============================================================================
// A: transpose (row, t) -> (t+EDGE, row) into the extended buffer
// ============================================================================
__global__ __launch_bounds__(256)
void transpose_kernel(const float* __restrict__ x)
{
    __shared__ float tile[32][33];
    const int tbase = blockIdx.x * 32;
    const int rbase = blockIdx.y * 32;
    const int tx = threadIdx.x, ty = threadIdx.y;   // 32 x 8
    #pragma unroll
    for (int j = 0; j < 32; j += 8)
        tile[ty + j][tx] = x[(size_t)(rbase + ty + j) * T_LEN + tbase + tx];
    __syncthreads();
    #pragma unroll
    for (int j = 0; j < 32; j += 8)
        g_xTe[(size_t)(tbase + ty + j + EDGE) * N_ROWS + rbase + tx] = tile[tx][ty + j];
}

// A2: fill the 2*EDGE odd-extension rows (after transpose)
__global__ __launch_bounds__(N_ROWS)
void edge_ext_kernel()
{
    const int r = threadIdx.x;
    const float x0 = g_xTe[(size_t)EDGE * N_ROWS + r];
    const float xL = g_xTe[(size_t)(T_LEN - 1 + EDGE) * N_ROWS + r];
    #pragma unroll
    for (int e = 0; e < EDGE; ++e)
        g_xTe[(size_t)e * N_ROWS + r] =
            2.0f * x0 - g_xTe[(size_t)(2 * EDGE - e) * N_ROWS + r];
    #pragma unroll
    for (int e = 0; e < EDGE; ++e) {
        int u = T_LEN + e;
        g_xTe[(size_t)(TEXT - EDGE + e) * N_ROWS + r] =
            2.0f * xL - g_xTe[(size_t)(2 * T_LEN - 2 - u + EDGE) * N_ROWS + r];
    }
}

// ============================================================================
// B1: forward phase1 — zero-state chunk run, 8-wide prefetch.
// ============================================================================
__global__ __launch_bounds__(256)
void iir_phase1_fwd(const float* __restrict__ b, const float* __restrict__ a)
{
    const int w    = (blockIdx.x * 256 + threadIdx.x) >> 5;
    const int lane = threadIdx.x & 31;
    const int p    = w % P_CH;
    const int rg   = w / P_CH;
    const int r    = rg * 32 + lane;

    const float b0 = b[0], b1 = b[1], b2 = b[2];
    const float a1 = a[1], a2 = a[2];

    const int s = p * L_CH;
    const int len = chunk_len(s);

    float z1 = 0.f, z2 = 0.f, y;
    int i = s;
    const int e8 = s + (len & ~7);
    for (; i < e8; i += 8) {
        float xb[8];
        #pragma unroll
        for (int u = 0; u < 8; ++u)
            xb[u] = g_xTe[(size_t)(i + u) * N_ROWS + r];
        #pragma unroll
        for (int u = 0; u < 8; ++u)
            iir_step(xb[u], z1, z2, b0, b1, b2, a1, a2, y);
    }
    for (; i < s + len; ++i)
        iir_step(g_xTe[(size_t)i * N_ROWS + r], z1, z2, b0, b1, b2, a1, a2, y);

    g_V1[p * N_ROWS + r] = z1;
    g_V2[p * N_ROWS + r] = z2;
}

// ============================================================================
// B2/B4: PARALLEL scan — one block per row, 512 threads = 512 scan positions.
// Forward: scan position q = physical chunk q (ascending).
// Backward: scan position q = physical chunk P_CH-1-q (descending physical).
// Kogge-Stone inclusive scan over affine maps; thread q applies its EXCLUSIVE
// prefix to z_init and stores the state entering its PHYSICAL chunk.
// Composition (older map first): (M,v) = (Mp*Mq, Mp*vq + vp).
// ============================================================================
__global__ __launch_bounds__(P_CH)
void iir_scan_par(const float* __restrict__ a, const float* __restrict__ zi,
                  int backward)
{
    __shared__ float sm00[P_CH], sm01[P_CH], sm10[P_CH], sm11[P_CH];
    __shared__ float sv1 [P_CH], sv2 [P_CH];

    const int row = blockIdx.x;
    const int q   = threadIdx.x;                       // scan position
    const int c   = backward ? (P_CH - 1 - q) : q;     // physical chunk
    const float a1 = a[1], a2 = a[2];

    float m00, m01, m10, m11;
    a_pow(chunk_len(c * L_CH), a1, a2, m00, m01, m10, m11);
    float v1 = g_V1[c * N_ROWS + row];
    float v2 = g_V2[c * N_ROWS + row];

    sm00[q] = m00; sm01[q] = m01; sm10[q] = m10; sm11[q] = m11;
    sv1[q] = v1;   sv2[q] = v2;
    __syncthreads();

    #pragma unroll
    for (int d = 1; d < P_CH; d <<= 1) {
        float q00 = 0.f, q01 = 0.f, q10 = 0.f, q11 = 0.f, qv1 = 0.f, qv2 = 0.f;
        if (q >= d) {
            q00 = sm00[q - d]; q01 = sm01[q - d];
            q10 = sm10[q - d]; q11 = sm11[q - d];
            qv1 = sv1[q - d];  qv2 = sv2[q - d];
        }
        __syncthreads();
        if (q >= d) {
            float n00 = m00*q00 + m01*q10, n01 = m00*q01 + m01*q11;
            float n10 = m10*q00 + m11*q10, n11 = m10*q01 + m11*q11;
            float nv1 = m00*qv1 + m01*qv2 + v1;
            float nv2 = m10*qv1 + m11*qv2 + v2;
            m00 = n00; m01 = n01; m10 = n10; m11 = n11; v1 = nv1; v2 = nv2;
            sm00[q] = m00; sm01[q] = m01; sm10[q] = m10; sm11[q] = m11;
            sv1[q] = v1;   sv2[q] = v2;
        }
        __syncthreads();
    }

    // z_init = zi * (first sample of the stream)
    float e0 = backward ? g_yfT[(size_t)(TEXT - 1) * N_ROWS + row]
                        : g_xTe[row];
    float zi1 = zi[0] * e0, zi2 = zi[1] * e0;
    float z1, z2;
    if (q == 0) { z1 = zi1; z2 = zi2; }
    else {
        float p00 = sm00[q-1], p01 = sm01[q-1], p10 = sm10[q-1], p11 = sm11[q-1];
        z1 = p00*zi1 + p01*zi2 + sv1[q-1];
        z2 = p10*zi1 + p11*zi2 + sv2[q-1];
    }
    g_Z1[c * N_ROWS + row] = z1;
    g_Z2[c * N_ROWS + row] = z2;
}

// ============================================================================
// B3: FUSED forward phase2 + backward phase1 (8-wide prefetch both loops).
//  1) corrected forward recursion over the chunk, write yfT
//  2) backward zero-state recursion over the SAME chunk in reverse
//     (backward pass == same samples visited in descending physical order).
//     Re-reads are this thread's own just-written values: per-thread ordered.
// ============================================================================
__global__ __launch_bounds__(256)
void iir_mid(const float* __restrict__ b, const float* __restrict__ a)
{
    const int w    = (blockIdx.x * 256 + threadIdx.x) >> 5;
    const int lane = threadIdx.x & 31;
    const int p    = w % P_CH;
    const int rg   = w / P_CH;
    const int r    = rg * 32 + lane;

    const float b0 = b[0], b1 = b[1], b2 = b[2];
    const float a1 = a[1], a2 = a[2];

    const int s = p * L_CH;
    const int len = chunk_len(s);

    // forward phase2
    float z1 = g_Z1[p * N_ROWS + r];
    float z2 = g_Z2[p * N_ROWS + r];
    float y;
    int i = s;
    const int e8 = s + (len & ~7);
    for (; i < e8; i += 8) {
        float xb[8];
        #pragma unroll
        for (int u = 0; u < 8; ++u)
            xb[u] = g_xTe[(size_t)(i + u) * N_ROWS + r];
        #pragma unroll
        for (int u = 0; u < 8; ++u) {
            iir_step(xb[u], z1, z2, b0, b1, b2, a1, a2, y);
            g_yfT[(size_t)(i + u) * N_ROWS + r] = y;
        }
    }
    for (; i < s + len; ++i) {
        iir_step(g_xTe[(size_t)i * N_ROWS + r], z1, z2, b0, b1, b2, a1, a2, y);
        g_yfT[(size_t)i * N_ROWS + r] = y;
    }

    // backward phase1: zero-state run over the SAME chunk, descending.
    float bz1 = 0.f, bz2 = 0.f;
    int j = s + len - 1;
    const int cnt8 = len & ~7;
    for (int c = 0; c < cnt8; c += 8, j -= 8) {
        float xb[8];
        #pragma unroll
        for (int u = 0; u < 8; ++u)
            xb[u] = g_yfT[(size_t)(j - u) * N_ROWS + r];
        #pragma unroll
        for (int u = 0; u < 8; ++u)
            iir_step(xb[u], bz1, bz2, b0, b1, b2, a1, a2, y);
    }
    for (; j >= s; --j)
        iir_step(g_yfT[(size_t)j * N_ROWS + r], bz1, bz2, b0, b1, b2, a1, a2, y);

    g_V1[p * N_ROWS + r] = bz1;
    g_V2[p * N_ROWS + r] = bz2;
}

// ============================================================================
// B5: backward phase2 — physical chunk p processed descending; output
// index t = i - EDGE; row-major writes via per-warp 32x32 smem staging.
// 8-wide prefetch inside the 32-sample staging blocks.
// ============================================================================
__global__ __launch_bounds__(256)
void iir_phase2_bwd(const float* __restrict__ b, const float* __restrict__ a)
{
    __shared__ float stile[8][32][33];
    const int wib  = threadIdx.x >> 5;
    float (*sS)[33] = stile[wib];

    const int w    = (blockIdx.x * 256 + threadIdx.x) >> 5;
    const int lane = threadIdx.x & 31;
    const int p    = w % P_CH;
    const int rg   = w / P_CH;
    const int r    = rg * 32 + lane;
    const int rowbase = rg * 32;

    const float b0 = b[0], b1 = b[1], b2 = b[2];
    const float a1 = a[1], a2 = a[2];

    const int s = p * L_CH;
    const int len = chunk_len(s);

    float z1 = g_Z1[p * N_ROWS + r];
    float z2 = g_Z2[p * N_ROWS + r];
    float y;

    int i = s + len - 1;                     // descending physical index
    int remaining = len;
    while (remaining > 0) {
        const int itop = i;
        int cnt = remaining < 32 ? remaining : 32;
        if (cnt == 32) {
            #pragma unroll 1
            for (int c = 0; c < 32; c += 8) {
                float xb[8];
                #pragma unroll
                for (int u = 0; u < 8; ++u)
                    xb[u] = g_yfT[(size_t)(i - u) * N_ROWS + r];
                #pragma unroll
                for (int u = 0; u < 8; ++u) {
                    iir_step(xb[u], z1, z2, b0, b1, b2, a1, a2, y);
                    sS[lane][c + u] = y;
                }
                i -= 8;
            }
        } else {
            for (int c = 0; c < cnt; ++c, --i) {
                iir_step(g_yfT[(size_t)i * N_ROWS + r],
                         z1, z2, b0, b1, b2, a1, a2, y);
                sS[lane][c] = y;
            }
        }
        remaining -= cnt;
        __syncwarp();
        // column c holds time t = itop - c - EDGE for each staged row
        const int ttop = itop - EDGE;
        const int t2 = ttop - lane;
        const bool ok = (lane < cnt) && (t2 >= 0) && (t2 < T_LEN);
        #pragma unroll 4
        for (int rr = 0; rr < 32; ++rr) {
            float v = sS[rr][lane];
            if (ok) g_mid[(size_t)(rowbase + rr) * T_LEN + t2] = v;
        }
        __syncwarp();
    }
}

// ============================================================================
// D: 301-tap conv, packed f32x2 with dual-parity smem copies
// ============================================================================
__global__ __launch_bounds__(F_THREADS)
void fir_kernel(float* __restrict__ out)
{
    __shared__ __align__(16) float  sT [F_SM];
    __shared__ __align__(16) float  sTs[F_SM];
    __shared__ __align__(16) float2 sG2[G_TAPS + 1];

    const int row = blockIdx.y;
    const int t0  = blockIdx.x * F_TILE;
    const float* xr   = g_mid + (size_t)row * T_LEN;
    float*       outr = out   + (size_t)row * T_LEN;

    for (int j = threadIdx.x; j < F_EXT; j += F_THREADS)
        sT[j] = odd_ext_load(xr, t0 - HALO + j);
    for (int j = threadIdx.x; j < G_TAPS; j += F_THREADS) {
        float g = g_comb[j];
        sG2[j] = make_float2(g, g);
    }
    __syncthreads();
    for (int j = threadIdx.x; j < F_EXT - 1; j += F_THREADS)
        sTs[j] = sT[j + 1];
    __syncthreads();

    const int base = threadIdx.x * F_RPT;       // even
    float2 acc[4];
    float2 wE[8], wO[8];
    #pragma unroll
    for (int j = 0; j < 4; ++j) acc[j] = make_float2(0.f, 0.f);
    #pragma unroll
    for (int m = 0; m < 8; ++m) {
        wE[m] = *reinterpret_cast<const float2*>(&sT [base + 2 * m]);
        wO[m] = *reinterpret_cast<const float2*>(&sTs[base + 2 * m]);
    }

    #pragma unroll 1
    for (int kb2 = 0; kb2 < 288; kb2 += 16) {
        const int K0 = kb2 >> 1;
        #pragma unroll
        for (int h = 0; h < 2; ++h) {
            #pragma unroll
            for (int j = 0; j < 4; ++j) {
                const int k = kb2 + h * 8 + 2 * j;
                const float2 ge = sG2[k];
                const float2 go = sG2[k + 1];
                #pragma unroll
                for (int jj = 0; jj < 4; ++jj)
                    ffma2(acc[jj], ge, wE[(h * 4 + j + jj) & 7]);
                #pragma unroll
                for (int jj = 0; jj < 4; ++jj)
                    ffma2(acc[jj], go, wO[(h * 4 + j + jj) & 7]);
                const int np = K0 + h * 4 + 8 + j;
                wE[(h * 4 + j) & 7] = *reinterpret_cast<const float2*>(&sT [base + 2 * np]);
                wO[(h * 4 + j) & 7] = *reinterpret_cast<const float2*>(&sTs[base + 2 * np]);
            }
        }
    }

    #pragma unroll
    for (int k = 288; k < G_TAPS; ++k) {
        const float gk = sG2[k].x;
        #pragma unroll
        for (int j = 0; j < 4; ++j) {
            acc[j].x = fmaf(gk, sT[base + k + 2 * j],     acc[j].x);
            acc[j].y = fmaf(gk, sT[base + k + 2 * j + 1], acc[j].y);
        }
    }

    const int tg = t0 + base;
    #pragma unroll
    for (int j = 0; j < 4; ++j) {
        int t = tg + 2 * j;
        if (t < T_LEN)     outr[t]     = acc[j].x;
        if (t + 1 < T_LEN) outr[t + 1] = acc[j].y;
    }
}

// ============================================================================
// Inputs (metadata order): x, b_notch(3), a_notch(3), zi_notch(2),
//                          b_fir(151), zi_fir (provably unused)
// ============================================================================
extern "C" void kernel_launch(void* const* d_in, const int* in_sizes, int n_in,
                              void* d_out, int out_size)
{
    const float* x  = (const float*)d_in[0];
    const float* bn = (const float*)d_in[1];
    const float* an = (const float*)d_in[2];
    const float* zn = (const float*)d_in[3];
    const float* bf = (const float*)d_in[4];
    float* out = (float*)d_out;

    comb_kernel<<<1, 320>>>(bf);                 // launch 0 (independent)

    dim3 tgrid(T_LEN / 32, N_ROWS / 32);
    transpose_kernel<<<tgrid, dim3(32, 8)>>>(x); // 1
    edge_ext_kernel<<<1, N_ROWS>>>();            // 2

    iir_phase1_fwd<<<IIR_BLOCKS, 256>>>(bn, an); // 3
    iir_scan_par<<<N_ROWS, P_CH>>>(an, zn, 0);   // 4
    iir_mid<<<IIR_BLOCKS, 256>>>(bn, an);        // 5  <- profiled by ncu -s 5
    iir_scan_par<<<N_ROWS, P_CH>>>(an, zn, 1);   // 6
    iir_phase2_bwd<<<IIR_BLOCKS, 256>>>(bn, an); // 7

    dim3 fgrid((T_LEN + F_TILE - 1) / F_TILE, N_ROWS);
    fir_kernel<<<fgrid, F_THREADS>>>(out);       // 8
}

// round 13
// speedup vs baseline: 2.2064x; 1.0307x over previous
#include <cuda_runtime.h>

// ============================================================================
// EcgFilter — round 12: revert to R10-passing pipeline; rebuild FIR for the
// smem-crossbar bottleneck (F_RPT 16, packed tap broadcast, dual-parity
// windows). tcgen05 is unavailable: harness PTX target is compute_100
// (no 'a' features) — confirmed by R11 ptxas errors. Do not retry.
// ============================================================================

#define T_LEN   120000
#define N_ROWS  384
#define EDGE    9
#define TEXT    (T_LEN + 2*EDGE)             // 120018
#define P_CH    512
#define L_CH    ((TEXT + P_CH - 1) / P_CH)   // 235
#define RG      (N_ROWS / 32)
#define IIR_WARPS (RG * P_CH)
#define IIR_BLOCKS (IIR_WARPS / 8)

#define FIR_TAPS 151
#define G_TAPS   301
#define HALO     150
#define F_THREADS 256
#define F_RPT     16
#define F_TILE    (F_THREADS * F_RPT)        // 4096 outputs per block
#define F_EXT     (F_TILE + 2*HALO)          // 4396
#define F_SM      (F_EXT + 8)
#define NPAIR     152                        // tap pairs (301 taps -> 151, pad)

// ---------------- scratch (static __device__: allocation-free rule) --------
__device__ float g_xTe[(size_t)TEXT * N_ROWS];
__device__ float g_yfT[(size_t)TEXT * N_ROWS];
__device__ float g_mid[(size_t)N_ROWS * T_LEN];
__device__ float g_V1[P_CH * N_ROWS], g_V2[P_CH * N_ROWS];
__device__ float g_Z1[P_CH * N_ROWS], g_Z2[P_CH * N_ROWS];
__device__ float g_comb[G_TAPS];

__device__ __forceinline__ int chunk_len(int s)
{
    int len = TEXT - s;
    len = len < L_CH ? len : L_CH;
    return len < 0 ? 0 : len;
}

__device__ __forceinline__ float odd_ext_load(const float* __restrict__ r, int u)
{
    if (u < 0)       return 2.0f * r[0]         - r[-u];
    if (u >= T_LEN)  return 2.0f * r[T_LEN - 1] - r[2 * T_LEN - 2 - u];
    return r[u];
}

// packed fp32 pair FMA (f32x2; legal under compute_100 — used in R10 pass)
__device__ __forceinline__ void ffma2(float2& d, const float2& a, const float2& b)
{
    asm("fma.rn.f32x2 %0, %1, %2, %0;"
        : "+l"(reinterpret_cast<unsigned long long&>(d))
        : "l"(reinterpret_cast<const unsigned long long&>(a)),
          "l"(reinterpret_cast<const unsigned long long&>(b)));
}

__device__ __forceinline__ void iir_step(float xn, float& z1, float& z2,
                                         float b0, float b1, float b2,
                                         float a1, float a2, float& y)
{
    y = fmaf(b0, xn, z1);
    float n1 = fmaf(b1, xn, z2) - a1 * y;
    float n2 = b2 * xn - a2 * y;
    z1 = n1; z2 = n2;
}

__device__ __forceinline__ void a_pow(int n, float a1, float a2,
                                      float& m00, float& m01, float& m10, float& m11)
{
    float c00 = -a1, c01 = 1.f, c10 = -a2, c11 = 0.f;
    float r00 = 1.f, r01 = 0.f, r10 = 0.f, r11 = 1.f;
    int e = n;
    while (e) {
        if (e & 1) {
            float t00 = r00*c00 + r01*c10, t01 = r00*c01 + r01*c11;
            float t10 = r10*c00 + r11*c10, t11 = r10*c01 + r11*c11;
            r00 = t00; r01 = t01; r10 = t10; r11 = t11;
        }
        e >>= 1;
        if (e) {
            float t00 = c00*c00 + c01*c10, t01 = c00*c01 + c01*c11;
            float t10 = c10*c00 + c11*c10, t11 = c10*c01 + c11*c11;
            c00 = t00; c01 = t01; c10 = t10; c11 = t11;
        }
    }
    m00 = r00; m01 = r01; m10 = r10; m11 = r11;
}

// ============================================================================
// C: g[d] = autocorrelation of b_fir
// ============================================================================
__global__ void comb_kernel(const float* __restrict__ bf)
{
    int k = threadIdx.x;
    if (k >= G_TAPS) return;
    int d = k - HALO;
    int j0 = d < 0 ? -d : 0;
    int j1 = d < 0 ? (FIR_TAPS - 1) : (FIR_TAPS - 1 - d);
    float acc = 0.f;
    for (int j = j0; j <= j1; ++j)
        acc = fmaf(bf[j], bf[j + d], acc);
    g_comb[k] = acc;
}

// ============================================================================
// A: transpose (row, t) -> (t+EDGE, row)
// ============================================================================
__global__ __launch_bounds__(256)
void transpose_kernel(const float* __restrict__ x)
{
    __shared__ float tile[32][33];
    const int tbase = blockIdx.x * 32, rbase = blockIdx.y * 32;
    const int tx = threadIdx.x, ty = threadIdx.y;
    #pragma unroll
    for (int j = 0; j < 32; j += 8)
        tile[ty + j][tx] = x[(size_t)(rbase + ty + j) * T_LEN + tbase + tx];
    __syncthreads();
    #pragma unroll
    for (int j = 0; j < 32; j += 8)
        g_xTe[(size_t)(tbase + ty + j + EDGE) * N_ROWS + rbase + tx] = tile[tx][ty + j];
}

__global__ __launch_bounds__(N_ROWS)
void edge_ext_kernel()
{
    const int r = threadIdx.x;
    const float x0 = g_xTe[(size_t)EDGE * N_ROWS + r];
    const float xL = g_xTe[(size_t)(T_LEN - 1 + EDGE) * N_ROWS + r];
    #pragma unroll
    for (int e = 0; e < EDGE; ++e)
        g_xTe[(size_t)e * N_ROWS + r] =
            2.0f * x0 - g_xTe[(size_t)(2 * EDGE - e) * N_ROWS + r];
    #pragma unroll
    for (int e = 0; e < EDGE; ++e) {
        int u = T_LEN + e;
        g_xTe[(size_t)(TEXT - EDGE + e) * N_ROWS + r] =
            2.0f * xL - g_xTe[(size_t)(2 * T_LEN - 2 - u + EDGE) * N_ROWS + r];
    }
}

// ============================================================================
// B1: forward phase1 — zero-state chunk run, 8-wide prefetch.
// ============================================================================
__global__ __launch_bounds__(256)
void iir_phase1_fwd(const float* __restrict__ b, const float* __restrict__ a)
{
    const int w = (blockIdx.x * 256 + threadIdx.x) >> 5;
    const int lane = threadIdx.x & 31;
    const int p = w % P_CH, rg = w / P_CH, r = rg * 32 + lane;
    const float b0 = b[0], b1 = b[1], b2 = b[2], a1 = a[1], a2 = a[2];
    const int s = p * L_CH, len = chunk_len(s);

    float z1 = 0.f, z2 = 0.f, y;
    int i = s;
    const int e8 = s + (len & ~7);
    for (; i < e8; i += 8) {
        float xb[8];
        #pragma unroll
        for (int u = 0; u < 8; ++u) xb[u] = g_xTe[(size_t)(i + u) * N_ROWS + r];
        #pragma unroll
        for (int u = 0; u < 8; ++u) iir_step(xb[u], z1, z2, b0, b1, b2, a1, a2, y);
    }
    for (; i < s + len; ++i)
        iir_step(g_xTe[(size_t)i * N_ROWS + r], z1, z2, b0, b1, b2, a1, a2, y);
    g_V1[p * N_ROWS + r] = z1;
    g_V2[p * N_ROWS + r] = z2;
}

// ============================================================================
// B2/B4: Kogge-Stone parallel scan over affine maps (one block per row)
// ============================================================================
__global__ __launch_bounds__(P_CH)
void iir_scan_par(const float* __restrict__ a, const float* __restrict__ zi, int backward)
{
    __shared__ float sm00[P_CH], sm01[P_CH], sm10[P_CH], sm11[P_CH];
    __shared__ float sv1[P_CH], sv2[P_CH];
    const int row = blockIdx.x, q = threadIdx.x;
    const int c = backward ? (P_CH - 1 - q) : q;
    const float a1 = a[1], a2 = a[2];

    float m00, m01, m10, m11;
    a_pow(chunk_len(c * L_CH), a1, a2, m00, m01, m10, m11);
    float v1 = g_V1[c * N_ROWS + row], v2 = g_V2[c * N_ROWS + row];
    sm00[q] = m00; sm01[q] = m01; sm10[q] = m10; sm11[q] = m11;
    sv1[q] = v1; sv2[q] = v2;
    __syncthreads();

    #pragma unroll
    for (int d = 1; d < P_CH; d <<= 1) {
        float q00 = 0.f, q01 = 0.f, q10 = 0.f, q11 = 0.f, qv1 = 0.f, qv2 = 0.f;
        if (q >= d) {
            q00 = sm00[q-d]; q01 = sm01[q-d]; q10 = sm10[q-d]; q11 = sm11[q-d];
            qv1 = sv1[q-d]; qv2 = sv2[q-d];
        }
        __syncthreads();
        if (q >= d) {
            float n00 = m00*q00 + m01*q10, n01 = m00*q01 + m01*q11;
            float n10 = m10*q00 + m11*q10, n11 = m10*q01 + m11*q11;
            float nv1 = m00*qv1 + m01*qv2 + v1;
            float nv2 = m10*qv1 + m11*qv2 + v2;
            m00 = n00; m01 = n01; m10 = n10; m11 = n11; v1 = nv1; v2 = nv2;
            sm00[q] = m00; sm01[q] = m01; sm10[q] = m10; sm11[q] = m11;
            sv1[q] = v1; sv2[q] = v2;
        }
        __syncthreads();
    }

    float e0 = backward ? g_yfT[(size_t)(TEXT - 1) * N_ROWS + row] : g_xTe[row];
    float zi1 = zi[0] * e0, zi2 = zi[1] * e0;
    float z1, z2;
    if (q == 0) { z1 = zi1; z2 = zi2; }
    else {
        z1 = sm00[q-1]*zi1 + sm01[q-1]*zi2 + sv1[q-1];
        z2 = sm10[q-1]*zi1 + sm11[q-1]*zi2 + sv2[q-1];
    }
    g_Z1[c * N_ROWS + row] = z1;
    g_Z2[c * N_ROWS + row] = z2;
}

// ============================================================================
// B3: FUSED forward phase2 + backward phase1
// ============================================================================
__global__ __launch_bounds__(256)
void iir_mid(const float* __restrict__ b, const float* __restrict__ a)
{
    const int w = (blockIdx.x * 256 + threadIdx.x) >> 5;
    const int lane = threadIdx.x & 31;
    const int p = w % P_CH, rg = w / P_CH, r = rg * 32 + lane;
    const float b0 = b[0], b1 = b[1], b2 = b[2], a1 = a[1], a2 = a[2];
    const int s = p * L_CH, len = chunk_len(s);

    float z1 = g_Z1[p * N_ROWS + r], z2 = g_Z2[p * N_ROWS + r], y;
    int i = s;
    const int e8 = s + (len & ~7);
    for (; i < e8; i += 8) {
        float xb[8];
        #pragma unroll
        for (int u = 0; u < 8; ++u) xb[u] = g_xTe[(size_t)(i + u) * N_ROWS + r];
        #pragma unroll
        for (int u = 0; u < 8; ++u) {
            iir_step(xb[u], z1, z2, b0, b1, b2, a1, a2, y);
            g_yfT[(size_t)(i + u) * N_ROWS + r] = y;
        }
    }
    for (; i < s + len; ++i) {
        iir_step(g_xTe[(size_t)i * N_ROWS + r], z1, z2, b0, b1, b2, a1, a2, y);
        g_yfT[(size_t)i * N_ROWS + r] = y;
    }

    float bz1 = 0.f, bz2 = 0.f;
    int j = s + len - 1;
    const int cnt8 = len & ~7;
    for (int c = 0; c < cnt8; c += 8, j -= 8) {
        float xb[8];
        #pragma unroll
        for (int u = 0; u < 8; ++u) xb[u] = g_yfT[(size_t)(j - u) * N_ROWS + r];
        #pragma unroll
        for (int u = 0; u < 8; ++u) iir_step(xb[u], bz1, bz2, b0, b1, b2, a1, a2, y);
    }
    for (; j >= s; --j)
        iir_step(g_yfT[(size_t)j * N_ROWS + r], bz1, bz2, b0, b1, b2, a1, a2, y);
    g_V1[p * N_ROWS + r] = bz1;
    g_V2[p * N_ROWS + r] = bz2;
}

// ============================================================================
// B5: backward phase2 -> g_mid row-major via per-warp smem staging
// ============================================================================
__global__ __launch_bounds__(256)
void iir_phase2_bwd(const float* __restrict__ b, const float* __restrict__ a)
{
    __shared__ float stile[8][32][33];
    const int wib = threadIdx.x >> 5;
    float (*sS)[33] = stile[wib];

    const int w = (blockIdx.x * 256 + threadIdx.x) >> 5;
    const int lane = threadIdx.x & 31;
    const int p = w % P_CH, rg = w / P_CH, r = rg * 32 + lane;
    const int rowbase = rg * 32;
    const float b0 = b[0], b1 = b[1], b2 = b[2], a1 = a[1], a2 = a[2];
    const int s = p * L_CH, len = chunk_len(s);

    float z1 = g_Z1[p * N_ROWS + r], z2 = g_Z2[p * N_ROWS + r], y;
    int i = s + len - 1;
    int remaining = len;
    while (remaining > 0) {
        const int itop = i;
        int cnt = remaining < 32 ? remaining : 32;
        if (cnt == 32) {
            #pragma unroll 1
            for (int c = 0; c < 32; c += 8) {
                float xb[8];
                #pragma unroll
                for (int u = 0; u < 8; ++u) xb[u] = g_yfT[(size_t)(i - u) * N_ROWS + r];
                #pragma unroll
                for (int u = 0; u < 8; ++u) {
                    iir_step(xb[u], z1, z2, b0, b1, b2, a1, a2, y);
                    sS[lane][c + u] = y;
                }
                i -= 8;
            }
        } else {
            for (int c = 0; c < cnt; ++c, --i) {
                iir_step(g_yfT[(size_t)i * N_ROWS + r], z1, z2, b0, b1, b2, a1, a2, y);
                sS[lane][c] = y;
            }
        }
        remaining -= cnt;
        __syncwarp();
        const int ttop = itop - EDGE;
        const int t2 = ttop - lane;
        const bool ok = (lane < cnt) && (t2 >= 0) && (t2 < T_LEN);
        #pragma unroll 4
        for (int rr = 0; rr < 32; ++rr) {
            float v = sS[rr][lane];
            if (ok) g_mid[(size_t)(rowbase + rr) * T_LEN + t2] = v;
        }
        __syncwarp();
    }
}

// ============================================================================
// D: 301-tap conv, rebuilt for the smem bottleneck:
//  - 16 outputs/thread = 8 float2 accumulators (2x arithmetic per LDS)
//  - taps broadcast as ONE LDS.128 per tap pair: sG4[kp]={ge,ge,go,go}
//  - dual-parity arrays sT / sTs(+1 shift); depth-8 rotating pair windows
//  - per tap pair: 16 FFMA2 vs 2 window LDS.64 + 1 broadcast LDS.128
// ============================================================================
__global__ __launch_bounds__(F_THREADS)
void fir_kernel(float* __restrict__ out)
{
    __shared__ __align__(16) float  sT [F_SM];
    __shared__ __align__(16) float  sTs[F_SM];
    __shared__ __align__(16) float4 sG4[NPAIR];

    const int row = blockIdx.y;
    const int t0  = blockIdx.x * F_TILE;
    const float* xr   = g_mid + (size_t)row * T_LEN;
    float*       outr = out   + (size_t)row * T_LEN;

    for (int j = threadIdx.x; j < F_EXT; j += F_THREADS)
        sT[j] = odd_ext_load(xr, t0 - HALO + j);
    for (int kp = threadIdx.x; kp < NPAIR; kp += F_THREADS) {
        float ge = (2*kp   < G_TAPS) ? g_comb[2*kp]   : 0.f;
        float go = (2*kp+1 < G_TAPS) ? g_comb[2*kp+1] : 0.f;
        sG4[kp] = make_float4(ge, ge, go, go);
    }
    __syncthreads();
    for (int j = threadIdx.x; j < F_EXT - 1; j += F_THREADS)
        sTs[j] = sT[j + 1];
    __syncthreads();

    const int base = threadIdx.x * F_RPT;      // even; pairs at base/2 + m
    float2 acc[8];
    float2 wE[8], wO[8];
    #pragma unroll
    for (int j = 0; j < 8; ++j) acc[j] = make_float2(0.f, 0.f);
    #pragma unroll
    for (int m = 0; m < 8; ++m) {
        wE[m] = *reinterpret_cast<const float2*>(&sT [base + 2 * m]);
        wO[m] = *reinterpret_cast<const float2*>(&sTs[base + 2 * m]);
    }

    // windowed tap pairs kp = 0..143 (taps 0..287)
    #pragma unroll 1
    for (int kp8 = 0; kp8 < 144; kp8 += 8) {
        #pragma unroll
        for (int q = 0; q < 8; ++q) {
            const int kp = kp8 + q;
            const float4 tp = sG4[kp];              // broadcast LDS.128
            const float2 ge = make_float2(tp.x, tp.y);
            const float2 go = make_float2(tp.z, tp.w);
            #pragma unroll
            for (int jj = 0; jj < 8; ++jj)
                ffma2(acc[jj], ge, wE[(q + jj) & 7]);
            #pragma unroll
            for (int jj = 0; jj < 8; ++jj)
                ffma2(acc[jj], go, wO[(q + jj) & 7]);
            // refill slot q with pair kp+8
            wE[q] = *reinterpret_cast<const float2*>(&sT [base + 2 * (kp + 8)]);
            wO[q] = *reinterpret_cast<const float2*>(&sTs[base + 2 * (kp + 8)]);
        }
    }

    // tail taps 288..300, packed via parity arrays (direct loads)
    #pragma unroll
    for (int k = 288; k < G_TAPS; ++k) {
        const float4 tp = sG4[k >> 1];
        const float gk = (k & 1) ? tp.z : tp.x;
        const float2 g2 = make_float2(gk, gk);
        const float* src = (k & 1) ? &sTs[base + k - 1] : &sT[base + k];
        #pragma unroll
        for (int jj = 0; jj < 8; ++jj) {
            float2 xv = *reinterpret_cast<const float2*>(src + 2 * jj);
            ffma2(acc[jj], g2, xv);
        }
    }

    const int tg = t0 + base;
    #pragma unroll
    for (int j = 0; j < 4; ++j) {
        int t = tg + 4 * j;
        float4 v = make_float4(acc[2*j].x, acc[2*j].y, acc[2*j+1].x, acc[2*j+1].y);
        if (t + 3 < T_LEN) {
            *reinterpret_cast<float4*>(outr + t) = v;
        } else {
            if (t + 0 < T_LEN) outr[t + 0] = v.x;
            if (t + 1 < T_LEN) outr[t + 1] = v.y;
            if (t + 2 < T_LEN) outr[t + 2] = v.z;
            if (t + 3 < T_LEN) outr[t + 3] = v.w;
        }
    }
}

// ============================================================================
// Inputs: x, b_notch(3), a_notch(3), zi_notch(2), b_fir(151), zi_fir (unused)
// ============================================================================
extern "C" void kernel_launch(void* const* d_in, const int* in_sizes, int n_in,
                              void* d_out, int out_size)
{
    const float* x  = (const float*)d_in[0];
    const float* bn = (const float*)d_in[1];
    const float* an = (const float*)d_in[2];
    const float* zn = (const float*)d_in[3];
    const float* bf = (const float*)d_in[4];
    float* out = (float*)d_out;

    comb_kernel<<<1, 320>>>(bf);                         // 0

    dim3 tgrid(T_LEN / 32, N_ROWS / 32);
    transpose_kernel<<<tgrid, dim3(32, 8)>>>(x);         // 1
    edge_ext_kernel<<<1, N_ROWS>>>();                    // 2

    iir_phase1_fwd<<<IIR_BLOCKS, 256>>>(bn, an);         // 3
    iir_scan_par<<<N_ROWS, P_CH>>>(an, zn, 0);           // 4
    iir_mid<<<IIR_BLOCKS, 256>>>(bn, an);                // 5
    iir_scan_par<<<N_ROWS, P_CH>>>(an, zn, 1);           // 6
    iir_phase2_bwd<<<IIR_BLOCKS, 256>>>(bn, an);         // 7

    dim3 fgrid((T_LEN + F_TILE - 1) / F_TILE, N_ROWS);
    fir_kernel<<<fgrid, F_THREADS>>>(out);               // 8
}

// round 14
// speedup vs baseline: 2.8135x; 1.2752x over previous
#include <cuda_runtime.h>

// ============================================================================
// EcgFilter — round 13: FFT overlap-save FIR (the structural win).
//   IIR filtfilt pipeline: byte-identical to R13 (passing, stream-roofline).
//   FIR: 301-tap symmetric conv == circular conv with real spectrum G.
//     - segments N=4096, overlap 2*150, useful L=3796, 32 segs/row
//     - TWO rows packed as re/im of one c2c FFT (G real => rows stay separate)
//     - radix-4 DIF fwd (natural->digitrev), pointwise *G, radix-4 DIT inv
//     - G computed in matching digit-rev order by running the SAME DIF on g
//   tcgen05 unavailable (compute_100 PTX target); f32x2 emulated — both dead ends.
// ============================================================================

#define T_LEN   120000
#define N_ROWS  384
#define EDGE    9
#define TEXT    (T_LEN + 2*EDGE)
#define P_CH    512
#define L_CH    ((TEXT + P_CH - 1) / P_CH)   // 235
#define RG      (N_ROWS / 32)
#define IIR_WARPS (RG * P_CH)
#define IIR_BLOCKS (IIR_WARPS / 8)

#define FIR_TAPS 151
#define G_TAPS   301
#define HALO     150

#define FFT_N   4096
#define SEG_L   (FFT_N - 2*HALO)             // 3796
#define NSEG    32                           // 32*3796 = 121472 >= 120000
#define SM_PAD(i) ((i) + ((i) >> 4))         // padded smem index (4352 floats)

// ---------------- scratch (static __device__: allocation-free rule) --------
__device__ float g_xTe[(size_t)TEXT * N_ROWS];
__device__ float g_yfT[(size_t)TEXT * N_ROWS];
__device__ float g_mid[(size_t)N_ROWS * T_LEN];
__device__ float g_V1[P_CH * N_ROWS], g_V2[P_CH * N_ROWS];
__device__ float g_Z1[P_CH * N_ROWS], g_Z2[P_CH * N_ROWS];
__device__ float g_comb[G_TAPS];
__device__ float2 g_tw[FFT_N];               // W_N^k = exp(-2*pi*i*k/N)
__device__ float  g_Grev[FFT_N];             // real spectrum of g, DIF order, /N

__device__ __forceinline__ int chunk_len(int s)
{
    int len = TEXT - s;
    len = len < L_CH ? len : L_CH;
    return len < 0 ? 0 : len;
}

__device__ __forceinline__ float odd_ext_load(const float* __restrict__ r, int u)
{
    if (u < 0)       return 2.0f * r[0]         - r[-u];
    if (u >= T_LEN)  return 2.0f * r[T_LEN - 1] - r[2 * T_LEN - 2 - u];
    return r[u];
}

__device__ __forceinline__ void iir_step(float xn, float& z1, float& z2,
                                         float b0, float b1, float b2,
                                         float a1, float a2, float& y)
{
    y = fmaf(b0, xn, z1);
    float n1 = fmaf(b1, xn, z2) - a1 * y;
    float n2 = b2 * xn - a2 * y;
    z1 = n1; z2 = n2;
}

__device__ __forceinline__ void a_pow(int n, float a1, float a2,
                                      float& m00, float& m01, float& m10, float& m11)
{
    float c00 = -a1, c01 = 1.f, c10 = -a2, c11 = 0.f;
    float r00 = 1.f, r01 = 0.f, r10 = 0.f, r11 = 1.f;
    int e = n;
    while (e) {
        if (e & 1) {
            float t00 = r00*c00 + r01*c10, t01 = r00*c01 + r01*c11;
            float t10 = r10*c00 + r11*c10, t11 = r10*c01 + r11*c11;
            r00 = t00; r01 = t01; r10 = t10; r11 = t11;
        }
        e >>= 1;
        if (e) {
            float t00 = c00*c00 + c01*c10, t01 = c00*c01 + c01*c11;
            float t10 = c10*c00 + c11*c10, t11 = c10*c01 + c11*c11;
            c00 = t00; c01 = t01; c10 = t10; c11 = t11;
        }
    }
    m00 = r00; m01 = r01; m10 = r10; m11 = r11;
}

// ============================================================================
// radix-4 in-place FFT, N=4096, 256 threads, 4 butterflies/thread/stage.
// FWD = DIF (natural -> digit-reversed), twiddle AFTER butterfly.
// INV = DIT (digit-reversed -> natural), CONJ twiddle BEFORE butterfly.
// smem arrays padded via SM_PAD. __syncthreads after every stage.
// ============================================================================
template<bool INV>
__device__ __forceinline__ void fft4096(float* sRe, float* sIm)
{
    const int tid = threadIdx.x;
    #pragma unroll 1
    for (int st = 0; st < 6; ++st) {
        const int s     = INV ? (1 << (2 * st)) : (1 << (10 - 2 * st));
        const int shift = INV ? (10 - 2 * st)   : (2 * st);
        #pragma unroll
        for (int m = 0; m < 4; ++m) {
            const int bf = tid + 256 * m;
            const int j  = bf & (s - 1);
            const int base = ((bf - j) << 2) + j;     // (bf/s)*4s + j
            const int p0 = SM_PAD(base);
            const int p1 = SM_PAD(base + s);
            const int p2 = SM_PAD(base + 2 * s);
            const int p3 = SM_PAD(base + 3 * s);
            float ar = sRe[p0], ai = sIm[p0];
            float br = sRe[p1], bi = sIm[p1];
            float cr = sRe[p2], ci = sIm[p2];
            float dr = sRe[p3], di = sIm[p3];
            const int tb = j << shift;
            const float2 w1 = g_tw[tb];
            const float2 w2 = g_tw[2 * tb];
            const float2 w3 = g_tw[3 * tb];
            if (INV) {
                // multiply b,c,d by conj(w): re = xr*wx + xi*wy ; im = xi*wx - xr*wy
                float t;
                t = br*w1.x + bi*w1.y;  bi = bi*w1.x - br*w1.y;  br = t;
                t = cr*w2.x + ci*w2.y;  ci = ci*w2.x - cr*w2.y;  cr = t;
                t = dr*w3.x + di*w3.y;  di = di*w3.x - dr*w3.y;  dr = t;
                float t0r = ar+cr, t0i = ai+ci, t1r = ar-cr, t1i = ai-ci;
                float t2r = br+dr, t2i = bi+di, t3r = br-dr, t3i = bi-di;
                sRe[p0] = t0r + t2r;  sIm[p0] = t0i + t2i;   // A = t0+t2
                sRe[p1] = t1r - t3i;  sIm[p1] = t1i + t3r;   // B = t1 + i*t3
                sRe[p2] = t0r - t2r;  sIm[p2] = t0i - t2i;   // C = t0-t2
                sRe[p3] = t1r + t3i;  sIm[p3] = t1i - t3r;   // D = t1 - i*t3
            } else {
                float t0r = ar+cr, t0i = ai+ci, t1r = ar-cr, t1i = ai-ci;
                float t2r = br+dr, t2i = bi+di, t3r = br-dr, t3i = bi-di;
                float Br = t1r + t3i, Bi = t1i - t3r;        // B = t1 - i*t3
                float Cr = t0r - t2r, Ci = t0i - t2i;        // C = t0-t2
                float Dr = t1r - t3i, Di = t1i + t3r;        // D = t1 + i*t3
                sRe[p0] = t0r + t2r;           sIm[p0] = t0i + t2i;
                sRe[p1] = Br*w1.x - Bi*w1.y;   sIm[p1] = Br*w1.y + Bi*w1.x;
                sRe[p2] = Cr*w2.x - Ci*w2.y;   sIm[p2] = Cr*w2.y + Ci*w2.x;
                sRe[p3] = Dr*w3.x - Di*w3.y;   sIm[p3] = Dr*w3.y + Di*w3.x;
            }
        }
        __syncthreads();
    }
}

// ============================================================================
// init kernels
// ============================================================================
__global__ void tw_init_kernel()
{
    int k = blockIdx.x * 256 + threadIdx.x;
    float s, c;
    sincospif((float)k / 2048.0f, &s, &c);   // theta = 2*pi*k/4096
    g_tw[k] = make_float2(c, -s);
}

__global__ void comb_kernel(const float* __restrict__ bf)
{
    int k = threadIdx.x;
    if (k >= G_TAPS) return;
    int d = k - HALO;
    int j0 = d < 0 ? -d : 0;
    int j1 = d < 0 ? (FIR_TAPS - 1) : (FIR_TAPS - 1 - d);
    float acc = 0.f;
    for (int j = j0; j <= j1; ++j)
        acc = fmaf(bf[j], bf[j + d], acc);
    g_comb[k] = acc;
}

// G in DIF output order: run the SAME forward FFT on circularly-placed g.
__global__ __launch_bounds__(256)
void gfft_init_kernel()
{
    __shared__ float sRe[FFT_N + 256], sIm[FFT_N + 256];
    const int tid = threadIdx.x;
    #pragma unroll
    for (int m = 0; m < 16; ++m) {
        int i = tid + 256 * m;
        float v = 0.f;
        if (i <= HALO)                 v = g_comb[HALO + i];
        else if (i >= FFT_N - HALO)    v = g_comb[HALO - (FFT_N - i)];
        sRe[SM_PAD(i)] = v;
        sIm[SM_PAD(i)] = 0.f;
    }
    __syncthreads();
    fft4096<false>(sRe, sIm);
    #pragma unroll
    for (int m = 0; m < 16; ++m) {
        int i = tid + 256 * m;
        g_Grev[i] = sRe[SM_PAD(i)] * (1.0f / (float)FFT_N);   // fold 1/N
    }
}

// ============================================================================
// IIR pipeline (identical to R13-passing)
// ============================================================================
__global__ __launch_bounds__(256)
void transpose_kernel(const float* __restrict__ x)
{
    __shared__ float tile[32][33];
    const int tbase = blockIdx.x * 32, rbase = blockIdx.y * 32;
    const int tx = threadIdx.x, ty = threadIdx.y;
    #pragma unroll
    for (int j = 0; j < 32; j += 8)
        tile[ty + j][tx] = x[(size_t)(rbase + ty + j) * T_LEN + tbase + tx];
    __syncthreads();
    #pragma unroll
    for (int j = 0; j < 32; j += 8)
        g_xTe[(size_t)(tbase + ty + j + EDGE) * N_ROWS + rbase + tx] = tile[tx][ty + j];
}

__global__ __launch_bounds__(N_ROWS)
void edge_ext_kernel()
{
    const int r = threadIdx.x;
    const float x0 = g_xTe[(size_t)EDGE * N_ROWS + r];
    const float xL = g_xTe[(size_t)(T_LEN - 1 + EDGE) * N_ROWS + r];
    #pragma unroll
    for (int e = 0; e < EDGE; ++e)
        g_xTe[(size_t)e * N_ROWS + r] =
            2.0f * x0 - g_xTe[(size_t)(2 * EDGE - e) * N_ROWS + r];
    #pragma unroll
    for (int e = 0; e < EDGE; ++e) {
        int u = T_LEN + e;
        g_xTe[(size_t)(TEXT - EDGE + e) * N_ROWS + r] =
            2.0f * xL - g_xTe[(size_t)(2 * T_LEN - 2 - u + EDGE) * N_ROWS + r];
    }
}

__global__ __launch_bounds__(256)
void iir_phase1_fwd(const float* __restrict__ b, const float* __restrict__ a)
{
    const int w = (blockIdx.x * 256 + threadIdx.x) >> 5;
    const int lane = threadIdx.x & 31;
    const int p = w % P_CH, rg = w / P_CH, r = rg * 32 + lane;
    const float b0 = b[0], b1 = b[1], b2 = b[2], a1 = a[1], a2 = a[2];
    const int s = p * L_CH, len = chunk_len(s);

    float z1 = 0.f, z2 = 0.f, y;
    int i = s;
    const int e8 = s + (len & ~7);
    for (; i < e8; i += 8) {
        float xb[8];
        #pragma unroll
        for (int u = 0; u < 8; ++u) xb[u] = g_xTe[(size_t)(i + u) * N_ROWS + r];
        #pragma unroll
        for (int u = 0; u < 8; ++u) iir_step(xb[u], z1, z2, b0, b1, b2, a1, a2, y);
    }
    for (; i < s + len; ++i)
        iir_step(g_xTe[(size_t)i * N_ROWS + r], z1, z2, b0, b1, b2, a1, a2, y);
    g_V1[p * N_ROWS + r] = z1;
    g_V2[p * N_ROWS + r] = z2;
}

__global__ __launch_bounds__(P_CH)
void iir_scan_par(const float* __restrict__ a, const float* __restrict__ zi, int backward)
{
    __shared__ float sm00[P_CH], sm01[P_CH], sm10[P_CH], sm11[P_CH];
    __shared__ float sv1[P_CH], sv2[P_CH];
    const int row = blockIdx.x, q = threadIdx.x;
    const int c = backward ? (P_CH - 1 - q) : q;
    const float a1 = a[1], a2 = a[2];

    float m00, m01, m10, m11;
    a_pow(chunk_len(c * L_CH), a1, a2, m00, m01, m10, m11);
    float v1 = g_V1[c * N_ROWS + row], v2 = g_V2[c * N_ROWS + row];
    sm00[q] = m00; sm01[q] = m01; sm10[q] = m10; sm11[q] = m11;
    sv1[q] = v1; sv2[q] = v2;
    __syncthreads();

    #pragma unroll
    for (int d = 1; d < P_CH; d <<= 1) {
        float q00 = 0.f, q01 = 0.f, q10 = 0.f, q11 = 0.f, qv1 = 0.f, qv2 = 0.f;
        if (q >= d) {
            q00 = sm00[q-d]; q01 = sm01[q-d]; q10 = sm10[q-d]; q11 = sm11[q-d];
            qv1 = sv1[q-d]; qv2 = sv2[q-d];
        }
        __syncthreads();
        if (q >= d) {
            float n00 = m00*q00 + m01*q10, n01 = m00*q01 + m01*q11;
            float n10 = m10*q00 + m11*q10, n11 = m10*q01 + m11*q11;
            float nv1 = m00*qv1 + m01*qv2 + v1;
            float nv2 = m10*qv1 + m11*qv2 + v2;
            m00 = n00; m01 = n01; m10 = n10; m11 = n11; v1 = nv1; v2 = nv2;
            sm00[q] = m00; sm01[q] = m01; sm10[q] = m10; sm11[q] = m11;
            sv1[q] = v1; sv2[q] = v2;
        }
        __syncthreads();
    }

    float e0 = backward ? g_yfT[(size_t)(TEXT - 1) * N_ROWS + row] : g_xTe[row];
    float zi1 = zi[0] * e0, zi2 = zi[1] * e0;
    float z1, z2;
    if (q == 0) { z1 = zi1; z2 = zi2; }
    else {
        z1 = sm00[q-1]*zi1 + sm01[q-1]*zi2 + sv1[q-1];
        z2 = sm10[q-1]*zi1 + sm11[q-1]*zi2 + sv2[q-1];
    }
    g_Z1[c * N_ROWS + row] = z1;
    g_Z2[c * N_ROWS + row] = z2;
}

__global__ __launch_bounds__(256)
void iir_mid(const float* __restrict__ b, const float* __restrict__ a)
{
    const int w = (blockIdx.x * 256 + threadIdx.x) >> 5;
    const int lane = threadIdx.x & 31;
    const int p = w % P_CH, rg = w / P_CH, r = rg * 32 + lane;
    const float b0 = b[0], b1 = b[1], b2 = b[2], a1 = a[1], a2 = a[2];
    const int s = p * L_CH, len = chunk_len(s);

    float z1 = g_Z1[p * N_ROWS + r], z2 = g_Z2[p * N_ROWS + r], y;
    int i = s;
    const int e8 = s + (len & ~7);
    for (; i < e8; i += 8) {
        float xb[8];
        #pragma unroll
        for (int u = 0; u < 8; ++u) xb[u] = g_xTe[(size_t)(i + u) * N_ROWS + r];
        #pragma unroll
        for (int u = 0; u < 8; ++u) {
            iir_step(xb[u], z1, z2, b0, b1, b2, a1, a2, y);
            g_yfT[(size_t)(i + u) * N_ROWS + r] = y;
        }
    }
    for (; i < s + len; ++i) {
        iir_step(g_xTe[(size_t)i * N_ROWS + r], z1, z2, b0, b1, b2, a1, a2, y);
        g_yfT[(size_t)i * N_ROWS + r] = y;
    }

    float bz1 = 0.f, bz2 = 0.f;
    int j = s + len - 1;
    const int cnt8 = len & ~7;
    for (int c = 0; c < cnt8; c += 8, j -= 8) {
        float xb[8];
        #pragma unroll
        for (int u = 0; u < 8; ++u) xb[u] = g_yfT[(size_t)(j - u) * N_ROWS + r];
        #pragma unroll
        for (int u = 0; u < 8; ++u) iir_step(xb[u], bz1, bz2, b0, b1, b2, a1, a2, y);
    }
    for (; j >= s; --j)
        iir_step(g_yfT[(size_t)j * N_ROWS + r], bz1, bz2, b0, b1, b2, a1, a2, y);
    g_V1[p * N_ROWS + r] = bz1;
    g_V2[p * N_ROWS + r] = bz2;
}

__global__ __launch_bounds__(256)
void iir_phase2_bwd(const float* __restrict__ b, const float* __restrict__ a)
{
    __shared__ float stile[8][32][33];
    const int wib = threadIdx.x >> 5;
    float (*sS)[33] = stile[wib];

    const int w = (blockIdx.x * 256 + threadIdx.x) >> 5;
    const int lane = threadIdx.x & 31;
    const int p = w % P_CH, rg = w / P_CH, r = rg * 32 + lane;
    const int rowbase = rg * 32;
    const float b0 = b[0], b1 = b[1], b2 = b[2], a1 = a[1], a2 = a[2];
    const int s = p * L_CH, len = chunk_len(s);

    float z1 = g_Z1[p * N_ROWS + r], z2 = g_Z2[p * N_ROWS + r], y;
    int i = s + len - 1;
    int remaining = len;
    while (remaining > 0) {
        const int itop = i;
        int cnt = remaining < 32 ? remaining : 32;
        if (cnt == 32) {
            #pragma unroll 1
            for (int c = 0; c < 32; c += 8) {
                float xb[8];
                #pragma unroll
                for (int u = 0; u < 8; ++u) xb[u] = g_yfT[(size_t)(i - u) * N_ROWS + r];
                #pragma unroll
                for (int u = 0; u < 8; ++u) {
                    iir_step(xb[u], z1, z2, b0, b1, b2, a1, a2, y);
                    sS[lane][c + u] = y;
                }
                i -= 8;
            }
        } else {
            for (int c = 0; c < cnt; ++c, --i) {
                iir_step(g_yfT[(size_t)i * N_ROWS + r], z1, z2, b0, b1, b2, a1, a2, y);
                sS[lane][c] = y;
            }
        }
        remaining -= cnt;
        __syncwarp();
        const int ttop = itop - EDGE;
        const int t2 = ttop - lane;
        const bool ok = (lane < cnt) && (t2 >= 0) && (t2 < T_LEN);
        #pragma unroll 4
        for (int rr = 0; rr < 32; ++rr) {
            float v = sS[rr][lane];
            if (ok) g_mid[(size_t)(rowbase + rr) * T_LEN + t2] = v;
        }
        __syncwarp();
    }
}

// ============================================================================
// FFT overlap-save conv: block = (segment, row-pair). Two rows packed re/im.
// ============================================================================
__global__ __launch_bounds__(256)
void fft_conv_kernel(float* __restrict__ out)
{
    __shared__ float sRe[FFT_N + 256], sIm[FFT_N + 256];
    const int tid = threadIdx.x;
    const int seg = blockIdx.x;
    const int rp  = blockIdx.y;
    const int row0 = 2 * rp, row1 = 2 * rp + 1;
    const int seg_start = seg * SEG_L;
    const float* x0 = g_mid + (size_t)row0 * T_LEN;
    const float* x1 = g_mid + (size_t)row1 * T_LEN;

    #pragma unroll
    for (int m = 0; m < 16; ++m) {
        int p = tid + 256 * m;
        int u = seg_start - HALO + p;
        int pp = SM_PAD(p);
        sRe[pp] = odd_ext_load(x0, u);
        sIm[pp] = odd_ext_load(x1, u);
    }
    __syncthreads();

    fft4096<false>(sRe, sIm);

    #pragma unroll
    for (int m = 0; m < 16; ++m) {
        int i = tid + 256 * m;
        float gv = g_Grev[i];
        int pp = SM_PAD(i);
        sRe[pp] *= gv;
        sIm[pp] *= gv;
    }
    __syncthreads();

    fft4096<true>(sRe, sIm);

    #pragma unroll
    for (int m = 0; m < 16; ++m) {
        int p = tid + 256 * m;
        if (p >= HALO && p < HALO + SEG_L) {
            int t = seg_start + p - HALO;
            if (t < T_LEN) {
                int pp = SM_PAD(p);
                out[(size_t)row0 * T_LEN + t] = sRe[pp];
                out[(size_t)row1 * T_LEN + t] = sIm[pp];
            }
        }
    }
}

// ============================================================================
// Inputs: x, b_notch(3), a_notch(3), zi_notch(2), b_fir(151), zi_fir (unused)
// ============================================================================
extern "C" void kernel_launch(void* const* d_in, const int* in_sizes, int n_in,
                              void* d_out, int out_size)
{
    const float* x  = (const float*)d_in[0];
    const float* bn = (const float*)d_in[1];
    const float* an = (const float*)d_in[2];
    const float* zn = (const float*)d_in[3];
    const float* bf = (const float*)d_in[4];
    float* out = (float*)d_out;

    tw_init_kernel<<<FFT_N / 256, 256>>>();              // 0
    comb_kernel<<<1, 320>>>(bf);                         // 1
    gfft_init_kernel<<<1, 256>>>();                      // 2

    dim3 tgrid(T_LEN / 32, N_ROWS / 32);
    transpose_kernel<<<tgrid, dim3(32, 8)>>>(x);         // 3
    edge_ext_kernel<<<1, N_ROWS>>>();                    // 4

    iir_phase1_fwd<<<IIR_BLOCKS, 256>>>(bn, an);         // 5
    iir_scan_par<<<N_ROWS, P_CH>>>(an, zn, 0);           // 6
    iir_mid<<<IIR_BLOCKS, 256>>>(bn, an);                // 7
    iir_scan_par<<<N_ROWS, P_CH>>>(an, zn, 1);           // 8
    iir_phase2_bwd<<<IIR_BLOCKS, 256>>>(bn, an);         // 9

    dim3 fgrid(NSEG, N_ROWS / 2);
    fft_conv_kernel<<<fgrid, 256>>>(out);                // 10
}

// round 15
// speedup vs baseline: 2.8246x; 1.0039x over previous
#include <cuda_runtime.h>

// ============================================================================
// EcgFilter — round 14: FFT conv was latency-bound (8 warps, 12 barriers).
//   * FFT kernel widened 256 -> 512 threads (2 butterflies/thread/stage,
//     identical indexing/arithmetic) — double-to-quadruple eligible warps.
//   * everything else byte-identical to the R14-passing kernel.
// ============================================================================

#define T_LEN   120000
#define N_ROWS  384
#define EDGE    9
#define TEXT    (T_LEN + 2*EDGE)
#define P_CH    512
#define L_CH    ((TEXT + P_CH - 1) / P_CH)   // 235
#define RG      (N_ROWS / 32)
#define IIR_WARPS (RG * P_CH)
#define IIR_BLOCKS (IIR_WARPS / 8)

#define FIR_TAPS 151
#define G_TAPS   301
#define HALO     150

#define FFT_N   4096
#define SEG_L   (FFT_N - 2*HALO)             // 3796
#define NSEG    32                           // 32*3796 >= 120000
#define FFT_THREADS 512
#define BF_PER  (FFT_N / 4 / FFT_THREADS)    // 2 butterflies/thread/stage
#define EL_PER  (FFT_N / FFT_THREADS)        // 8 elements/thread
#define SM_PAD(i) ((i) + ((i) >> 4))

// ---------------- scratch (static __device__: allocation-free rule) --------
__device__ float g_xTe[(size_t)TEXT * N_ROWS];
__device__ float g_yfT[(size_t)TEXT * N_ROWS];
__device__ float g_mid[(size_t)N_ROWS * T_LEN];
__device__ float g_V1[P_CH * N_ROWS], g_V2[P_CH * N_ROWS];
__device__ float g_Z1[P_CH * N_ROWS], g_Z2[P_CH * N_ROWS];
__device__ float g_comb[G_TAPS];
__device__ float2 g_tw[FFT_N];               // W_N^k = exp(-2*pi*i*k/N)
__device__ float  g_Grev[FFT_N];             // real spectrum of g, DIF order, /N

__device__ __forceinline__ int chunk_len(int s)
{
    int len = TEXT - s;
    len = len < L_CH ? len : L_CH;
    return len < 0 ? 0 : len;
}

__device__ __forceinline__ float odd_ext_load(const float* __restrict__ r, int u)
{
    if (u < 0)       return 2.0f * r[0]         - r[-u];
    if (u >= T_LEN)  return 2.0f * r[T_LEN - 1] - r[2 * T_LEN - 2 - u];
    return r[u];
}

__device__ __forceinline__ void iir_step(float xn, float& z1, float& z2,
                                         float b0, float b1, float b2,
                                         float a1, float a2, float& y)
{
    y = fmaf(b0, xn, z1);
    float n1 = fmaf(b1, xn, z2) - a1 * y;
    float n2 = b2 * xn - a2 * y;
    z1 = n1; z2 = n2;
}

__device__ __forceinline__ void a_pow(int n, float a1, float a2,
                                      float& m00, float& m01, float& m10, float& m11)
{
    float c00 = -a1, c01 = 1.f, c10 = -a2, c11 = 0.f;
    float r00 = 1.f, r01 = 0.f, r10 = 0.f, r11 = 1.f;
    int e = n;
    while (e) {
        if (e & 1) {
            float t00 = r00*c00 + r01*c10, t01 = r00*c01 + r01*c11;
            float t10 = r10*c00 + r11*c10, t11 = r10*c01 + r11*c11;
            r00 = t00; r01 = t01; r10 = t10; r11 = t11;
        }
        e >>= 1;
        if (e) {
            float t00 = c00*c00 + c01*c10, t01 = c00*c01 + c01*c11;
            float t10 = c10*c00 + c11*c10, t11 = c10*c01 + c11*c11;
            c00 = t00; c01 = t01; c10 = t10; c11 = t11;
        }
    }
    m00 = r00; m01 = r01; m10 = r10; m11 = r11;
}

// ============================================================================
// radix-4 in-place FFT, N=4096, FFT_THREADS threads, BF_PER butterflies each.
// FWD = DIF (natural -> digit-reversed), twiddle AFTER butterfly.
// INV = DIT (digit-reversed -> natural), CONJ twiddle BEFORE butterfly.
// ============================================================================
template<bool INV>
__device__ __forceinline__ void fft4096(float* sRe, float* sIm)
{
    const int tid = threadIdx.x;
    #pragma unroll 1
    for (int st = 0; st < 6; ++st) {
        const int s     = INV ? (1 << (2 * st)) : (1 << (10 - 2 * st));
        const int shift = INV ? (10 - 2 * st)   : (2 * st);
        #pragma unroll
        for (int m = 0; m < BF_PER; ++m) {
            const int bf = tid + FFT_THREADS * m;
            const int j  = bf & (s - 1);
            const int base = ((bf - j) << 2) + j;
            const int p0 = SM_PAD(base);
            const int p1 = SM_PAD(base + s);
            const int p2 = SM_PAD(base + 2 * s);
            const int p3 = SM_PAD(base + 3 * s);
            float ar = sRe[p0], ai = sIm[p0];
            float br = sRe[p1], bi = sIm[p1];
            float cr = sRe[p2], ci = sIm[p2];
            float dr = sRe[p3], di = sIm[p3];
            const int tb = j << shift;
            const float2 w1 = g_tw[tb];
            const float2 w2 = g_tw[2 * tb];
            const float2 w3 = g_tw[3 * tb];
            if (INV) {
                float t;
                t = br*w1.x + bi*w1.y;  bi = bi*w1.x - br*w1.y;  br = t;
                t = cr*w2.x + ci*w2.y;  ci = ci*w2.x - cr*w2.y;  cr = t;
                t = dr*w3.x + di*w3.y;  di = di*w3.x - dr*w3.y;  dr = t;
                float t0r = ar+cr, t0i = ai+ci, t1r = ar-cr, t1i = ai-ci;
                float t2r = br+dr, t2i = bi+di, t3r = br-dr, t3i = bi-di;
                sRe[p0] = t0r + t2r;  sIm[p0] = t0i + t2i;
                sRe[p1] = t1r - t3i;  sIm[p1] = t1i + t3r;
                sRe[p2] = t0r - t2r;  sIm[p2] = t0i - t2i;
                sRe[p3] = t1r + t3i;  sIm[p3] = t1i - t3r;
            } else {
                float t0r = ar+cr, t0i = ai+ci, t1r = ar-cr, t1i = ai-ci;
                float t2r = br+dr, t2i = bi+di, t3r = br-dr, t3i = bi-di;
                float Br = t1r + t3i, Bi = t1i - t3r;
                float Cr = t0r - t2r, Ci = t0i - t2i;
                float Dr = t1r - t3i, Di = t1i + t3r;
                sRe[p0] = t0r + t2r;           sIm[p0] = t0i + t2i;
                sRe[p1] = Br*w1.x - Bi*w1.y;   sIm[p1] = Br*w1.y + Bi*w1.x;
                sRe[p2] = Cr*w2.x - Ci*w2.y;   sIm[p2] = Cr*w2.y + Ci*w2.x;
                sRe[p3] = Dr*w3.x - Di*w3.y;   sIm[p3] = Dr*w3.y + Di*w3.x;
            }
        }
        __syncthreads();
    }
}

// ============================================================================
// init kernels
// ============================================================================
__global__ void tw_init_kernel()
{
    int k = blockIdx.x * 256 + threadIdx.x;
    float s, c;
    sincospif((float)k / 2048.0f, &s, &c);
    g_tw[k] = make_float2(c, -s);
}

__global__ void comb_kernel(const float* __restrict__ bf)
{
    int k = threadIdx.x;
    if (k >= G_TAPS) return;
    int d = k - HALO;
    int j0 = d < 0 ? -d : 0;
    int j1 = d < 0 ? (FIR_TAPS - 1) : (FIR_TAPS - 1 - d);
    float acc = 0.f;
    for (int j = j0; j <= j1; ++j)
        acc = fmaf(bf[j], bf[j + d], acc);
    g_comb[k] = acc;
}

// G in DIF output order: run the SAME forward FFT on circularly-placed g.
__global__ __launch_bounds__(FFT_THREADS)
void gfft_init_kernel()
{
    __shared__ float sRe[FFT_N + 256], sIm[FFT_N + 256];
    const int tid = threadIdx.x;
    #pragma unroll
    for (int m = 0; m < EL_PER; ++m) {
        int i = tid + FFT_THREADS * m;
        float v = 0.f;
        if (i <= HALO)                 v = g_comb[HALO + i];
        else if (i >= FFT_N - HALO)    v = g_comb[HALO - (FFT_N - i)];
        sRe[SM_PAD(i)] = v;
        sIm[SM_PAD(i)] = 0.f;
    }
    __syncthreads();
    fft4096<false>(sRe, sIm);
    #pragma unroll
    for (int m = 0; m < EL_PER; ++m) {
        int i = tid + FFT_THREADS * m;
        g_Grev[i] = sRe[SM_PAD(i)] * (1.0f / (float)FFT_N);
    }
}

// ============================================================================
// IIR pipeline (identical to R14-passing)
// ============================================================================
__global__ __launch_bounds__(256)
void transpose_kernel(const float* __restrict__ x)
{
    __shared__ float tile[32][33];
    const int tbase = blockIdx.x * 32, rbase = blockIdx.y * 32;
    const int tx = threadIdx.x, ty = threadIdx.y;
    #pragma unroll
    for (int j = 0; j < 32; j += 8)
        tile[ty + j][tx] = x[(size_t)(rbase + ty + j) * T_LEN + tbase + tx];
    __syncthreads();
    #pragma unroll
    for (int j = 0; j < 32; j += 8)
        g_xTe[(size_t)(tbase + ty + j + EDGE) * N_ROWS + rbase + tx] = tile[tx][ty + j];
}

__global__ __launch_bounds__(N_ROWS)
void edge_ext_kernel()
{
    const int r = threadIdx.x;
    const float x0 = g_xTe[(size_t)EDGE * N_ROWS + r];
    const float xL = g_xTe[(size_t)(T_LEN - 1 + EDGE) * N_ROWS + r];
    #pragma unroll
    for (int e = 0; e < EDGE; ++e)
        g_xTe[(size_t)e * N_ROWS + r] =
            2.0f * x0 - g_xTe[(size_t)(2 * EDGE - e) * N_ROWS + r];
    #pragma unroll
    for (int e = 0; e < EDGE; ++e) {
        int u = T_LEN + e;
        g_xTe[(size_t)(TEXT - EDGE + e) * N_ROWS + r] =
            2.0f * xL - g_xTe[(size_t)(2 * T_LEN - 2 - u + EDGE) * N_ROWS + r];
    }
}

__global__ __launch_bounds__(256)
void iir_phase1_fwd(const float* __restrict__ b, const float* __restrict__ a)
{
    const int w = (blockIdx.x * 256 + threadIdx.x) >> 5;
    const int lane = threadIdx.x & 31;
    const int p = w % P_CH, rg = w / P_CH, r = rg * 32 + lane;
    const float b0 = b[0], b1 = b[1], b2 = b[2], a1 = a[1], a2 = a[2];
    const int s = p * L_CH, len = chunk_len(s);

    float z1 = 0.f, z2 = 0.f, y;
    int i = s;
    const int e8 = s + (len & ~7);
    for (; i < e8; i += 8) {
        float xb[8];
        #pragma unroll
        for (int u = 0; u < 8; ++u) xb[u] = g_xTe[(size_t)(i + u) * N_ROWS + r];
        #pragma unroll
        for (int u = 0; u < 8; ++u) iir_step(xb[u], z1, z2, b0, b1, b2, a1, a2, y);
    }
    for (; i < s + len; ++i)
        iir_step(g_xTe[(size_t)i * N_ROWS + r], z1, z2, b0, b1, b2, a1, a2, y);
    g_V1[p * N_ROWS + r] = z1;
    g_V2[p * N_ROWS + r] = z2;
}

__global__ __launch_bounds__(P_CH)
void iir_scan_par(const float* __restrict__ a, const float* __restrict__ zi, int backward)
{
    __shared__ float sm00[P_CH], sm01[P_CH], sm10[P_CH], sm11[P_CH];
    __shared__ float sv1[P_CH], sv2[P_CH];
    const int row = blockIdx.x, q = threadIdx.x;
    const int c = backward ? (P_CH - 1 - q) : q;
    const float a1 = a[1], a2 = a[2];

    float m00, m01, m10, m11;
    a_pow(chunk_len(c * L_CH), a1, a2, m00, m01, m10, m11);
    float v1 = g_V1[c * N_ROWS + row], v2 = g_V2[c * N_ROWS + row];
    sm00[q] = m00; sm01[q] = m01; sm10[q] = m10; sm11[q] = m11;
    sv1[q] = v1; sv2[q] = v2;
    __syncthreads();

    #pragma unroll
    for (int d = 1; d < P_CH; d <<= 1) {
        float q00 = 0.f, q01 = 0.f, q10 = 0.f, q11 = 0.f, qv1 = 0.f, qv2 = 0.f;
        if (q >= d) {
            q00 = sm00[q-d]; q01 = sm01[q-d]; q10 = sm10[q-d]; q11 = sm11[q-d];
            qv1 = sv1[q-d]; qv2 = sv2[q-d];
        }
        __syncthreads();
        if (q >= d) {
            float n00 = m00*q00 + m01*q10, n01 = m00*q01 + m01*q11;
            float n10 = m10*q00 + m11*q10, n11 = m10*q01 + m11*q11;
            float nv1 = m00*qv1 + m01*qv2 + v1;
            float nv2 = m10*qv1 + m11*qv2 + v2;
            m00 = n00; m01 = n01; m10 = n10; m11 = n11; v1 = nv1; v2 = nv2;
            sm00[q] = m00; sm01[q] = m01; sm10[q] = m10; sm11[q] = m11;
            sv1[q] = v1; sv2[q] = v2;
        }
        __syncthreads();
    }

    float e0 = backward ? g_yfT[(size_t)(TEXT - 1) * N_ROWS + row] : g_xTe[row];
    float zi1 = zi[0] * e0, zi2 = zi[1] * e0;
    float z1, z2;
    if (q == 0) { z1 = zi1; z2 = zi2; }
    else {
        z1 = sm00[q-1]*zi1 + sm01[q-1]*zi2 + sv1[q-1];
        z2 = sm10[q-1]*zi1 + sm11[q-1]*zi2 + sv2[q-1];
    }
    g_Z1[c * N_ROWS + row] = z1;
    g_Z2[c * N_ROWS + row] = z2;
}

__global__ __launch_bounds__(256)
void iir_mid(const float* __restrict__ b, const float* __restrict__ a)
{
    const int w = (blockIdx.x * 256 + threadIdx.x) >> 5;
    const int lane = threadIdx.x & 31;
    const int p = w % P_CH, rg = w / P_CH, r = rg * 32 + lane;
    const float b0 = b[0], b1 = b[1], b2 = b[2], a1 = a[1], a2 = a[2];
    const int s = p * L_CH, len = chunk_len(s);

    float z1 = g_Z1[p * N_ROWS + r], z2 = g_Z2[p * N_ROWS + r], y;
    int i = s;
    const int e8 = s + (len & ~7);
    for (; i < e8; i += 8) {
        float xb[8];
        #pragma unroll
        for (int u = 0; u < 8; ++u) xb[u] = g_xTe[(size_t)(i + u) * N_ROWS + r];
        #pragma unroll
        for (int u = 0; u < 8; ++u) {
            iir_step(xb[u], z1, z2, b0, b1, b2, a1, a2, y);
            g_yfT[(size_t)(i + u) * N_ROWS + r] = y;
        }
    }
    for (; i < s + len; ++i) {
        iir_step(g_xTe[(size_t)i * N_ROWS + r], z1, z2, b0, b1, b2, a1, a2, y);
        g_yfT[(size_t)i * N_ROWS + r] = y;
    }

    float bz1 = 0.f, bz2 = 0.f;
    int j = s + len - 1;
    const int cnt8 = len & ~7;
    for (int c = 0; c < cnt8; c += 8, j -= 8) {
        float xb[8];
        #pragma unroll
        for (int u = 0; u < 8; ++u) xb[u] = g_yfT[(size_t)(j - u) * N_ROWS + r];
        #pragma unroll
        for (int u = 0; u < 8; ++u) iir_step(xb[u], bz1, bz2, b0, b1, b2, a1, a2, y);
    }
    for (; j >= s; --j)
        iir_step(g_yfT[(size_t)j * N_ROWS + r], bz1, bz2, b0, b1, b2, a1, a2, y);
    g_V1[p * N_ROWS + r] = bz1;
    g_V2[p * N_ROWS + r] = bz2;
}

__global__ __launch_bounds__(256)
void iir_phase2_bwd(const float* __restrict__ b, const float* __restrict__ a)
{
    __shared__ float stile[8][32][33];
    const int wib = threadIdx.x >> 5;
    float (*sS)[33] = stile[wib];

    const int w = (blockIdx.x * 256 + threadIdx.x) >> 5;
    const int lane = threadIdx.x & 31;
    const int p = w % P_CH, rg = w / P_CH, r = rg * 32 + lane;
    const int rowbase = rg * 32;
    const float b0 = b[0], b1 = b[1], b2 = b[2], a1 = a[1], a2 = a[2];
    const int s = p * L_CH, len = chunk_len(s);

    float z1 = g_Z1[p * N_ROWS + r], z2 = g_Z2[p * N_ROWS + r], y;
    int i = s + len - 1;
    int remaining = len;
    while (remaining > 0) {
        const int itop = i;
        int cnt = remaining < 32 ? remaining : 32;
        if (cnt == 32) {
            #pragma unroll 1
            for (int c = 0; c < 32; c += 8) {
                float xb[8];
                #pragma unroll
                for (int u = 0; u < 8; ++u) xb[u] = g_yfT[(size_t)(i - u) * N_ROWS + r];
                #pragma unroll
                for (int u = 0; u < 8; ++u) {
                    iir_step(xb[u], z1, z2, b0, b1, b2, a1, a2, y);
                    sS[lane][c + u] = y;
                }
                i -= 8;
            }
        } else {
            for (int c = 0; c < cnt; ++c, --i) {
                iir_step(g_yfT[(size_t)i * N_ROWS + r], z1, z2, b0, b1, b2, a1, a2, y);
                sS[lane][c] = y;
            }
        }
        remaining -= cnt;
        __syncwarp();
        const int ttop = itop - EDGE;
        const int t2 = ttop - lane;
        const bool ok = (lane < cnt) && (t2 >= 0) && (t2 < T_LEN);
        #pragma unroll 4
        for (int rr = 0; rr < 32; ++rr) {
            float v = sS[rr][lane];
            if (ok) g_mid[(size_t)(rowbase + rr) * T_LEN + t2] = v;
        }
        __syncwarp();
    }
}

// ============================================================================
// FFT overlap-save conv: block = (segment, row-pair). Two rows packed re/im.
// ============================================================================
__global__ __launch_bounds__(FFT_THREADS)
void fft_conv_kernel(float* __restrict__ out)
{
    __shared__ float sRe[FFT_N + 256], sIm[FFT_N + 256];
    const int tid = threadIdx.x;
    const int seg = blockIdx.x;
    const int rp  = blockIdx.y;
    const int row0 = 2 * rp, row1 = 2 * rp + 1;
    const int seg_start = seg * SEG_L;
    const float* x0 = g_mid + (size_t)row0 * T_LEN;
    const float* x1 = g_mid + (size_t)row1 * T_LEN;

    #pragma unroll
    for (int m = 0; m < EL_PER; ++m) {
        int p = tid + FFT_THREADS * m;
        int u = seg_start - HALO + p;
        int pp = SM_PAD(p);
        sRe[pp] = odd_ext_load(x0, u);
        sIm[pp] = odd_ext_load(x1, u);
    }
    __syncthreads();

    fft4096<false>(sRe, sIm);

    #pragma unroll
    for (int m = 0; m < EL_PER; ++m) {
        int i = tid + FFT_THREADS * m;
        float gv = g_Grev[i];
        int pp = SM_PAD(i);
        sRe[pp] *= gv;
        sIm[pp] *= gv;
    }
    __syncthreads();

    fft4096<true>(sRe, sIm);

    #pragma unroll
    for (int m = 0; m < EL_PER; ++m) {
        int p = tid + FFT_THREADS * m;
        if (p >= HALO && p < HALO + SEG_L) {
            int t = seg_start + p - HALO;
            if (t < T_LEN) {
                int pp = SM_PAD(p);
                out[(size_t)row0 * T_LEN + t] = sRe[pp];
                out[(size_t)row1 * T_LEN + t] = sIm[pp];
            }
        }
    }
}

// ============================================================================
// Inputs: x, b_notch(3), a_notch(3), zi_notch(2), b_fir(151), zi_fir (unused)
// ============================================================================
extern "C" void kernel_launch(void* const* d_in, const int* in_sizes, int n_in,
                              void* d_out, int out_size)
{
    const float* x  = (const float*)d_in[0];
    const float* bn = (const float*)d_in[1];
    const float* an = (const float*)d_in[2];
    const float* zn = (const float*)d_in[3];
    const float* bf = (const float*)d_in[4];
    float* out = (float*)d_out;

    tw_init_kernel<<<FFT_N / 256, 256>>>();              // 0
    comb_kernel<<<1, 320>>>(bf);                         // 1
    gfft_init_kernel<<<1, FFT_THREADS>>>();              // 2

    dim3 tgrid(T_LEN / 32, N_ROWS / 32);
    transpose_kernel<<<tgrid, dim3(32, 8)>>>(x);         // 3
    edge_ext_kernel<<<1, N_ROWS>>>();                    // 4

    iir_phase1_fwd<<<IIR_BLOCKS, 256>>>(bn, an);         // 5
    iir_scan_par<<<N_ROWS, P_CH>>>(an, zn, 0);           // 6
    iir_mid<<<IIR_BLOCKS, 256>>>(bn, an);                // 7
    iir_scan_par<<<N_ROWS, P_CH>>>(an, zn, 1);           // 8
    iir_phase2_bwd<<<IIR_BLOCKS, 256>>>(bn, an);         // 9

    dim3 fgrid(NSEG, N_ROWS / 2);
    fft_conv_kernel<<<fgrid, FFT_THREADS>>>(out);        // 10
}

// round 17
// speedup vs baseline: 3.9307x; 1.3916x over previous
#include <cuda_runtime.h>

// ============================================================================
// EcgFilter — round 16: resubmit R15 (infra failure, never benched).
// Kill the twiddle-scatter L1tex wavefront storm in the FFT conv.
//   Evidence: widening FFT blocks 256->512 was EXACTLY neutral => per-SM
//   serialized resource binds. tb = j<<shift twiddle LDGs touch up to 32
//   lines/warp in mid stages. Fix: per-stage contiguous twiddle tables
//   (tw1/tw2/tw3[LVL_OFF[lvl] + j], 1365 entries; same (s,shift) level set
//   serves DIF and DIT). All else byte-identical to the 1095.8us pass.
// ============================================================================

#define T_LEN   120000
#define N_ROWS  384
#define EDGE    9
#define TEXT    (T_LEN + 2*EDGE)
#define P_CH    512
#define L_CH    ((TEXT + P_CH - 1) / P_CH)   // 235
#define RG      (N_ROWS / 32)
#define IIR_WARPS (RG * P_CH)
#define IIR_BLOCKS (IIR_WARPS / 8)

#define FIR_TAPS 151
#define G_TAPS   301
#define HALO     150

#define FFT_N   4096
#define SEG_L   (FFT_N - 2*HALO)             // 3796
#define NSEG    32
#define FFT_THREADS 512
#define BF_PER  (FFT_N / 4 / FFT_THREADS)    // 2
#define EL_PER  (FFT_N / FFT_THREADS)        // 8
#define SM_PAD(i) ((i) + ((i) >> 4))
#define TW_TOTAL 1365                        // 1024+256+64+16+4+1

// ---------------- scratch (static __device__: allocation-free rule) --------
__device__ float g_xTe[(size_t)TEXT * N_ROWS];
__device__ float g_yfT[(size_t)TEXT * N_ROWS];
__device__ float g_mid[(size_t)N_ROWS * T_LEN];
__device__ float g_V1[P_CH * N_ROWS], g_V2[P_CH * N_ROWS];
__device__ float g_Z1[P_CH * N_ROWS], g_Z2[P_CH * N_ROWS];
__device__ float g_comb[G_TAPS];
__device__ float2 g_tw1[TW_TOTAL], g_tw2[TW_TOTAL], g_tw3[TW_TOTAL];
__device__ float  g_Grev[FFT_N];             // real spectrum of g, DIF order, /N

__constant__ int LVL_OFF[6] = {0, 1024, 1280, 1344, 1360, 1364};

__device__ __forceinline__ int chunk_len(int s)
{
    int len = TEXT - s;
    len = len < L_CH ? len : L_CH;
    return len < 0 ? 0 : len;
}

__device__ __forceinline__ float odd_ext_load(const float* __restrict__ r, int u)
{
    if (u < 0)       return 2.0f * r[0]         - r[-u];
    if (u >= T_LEN)  return 2.0f * r[T_LEN - 1] - r[2 * T_LEN - 2 - u];
    return r[u];
}

__device__ __forceinline__ void iir_step(float xn, float& z1, float& z2,
                                         float b0, float b1, float b2,
                                         float a1, float a2, float& y)
{
    y = fmaf(b0, xn, z1);
    float n1 = fmaf(b1, xn, z2) - a1 * y;
    float n2 = b2 * xn - a2 * y;
    z1 = n1; z2 = n2;
}

__device__ __forceinline__ void a_pow(int n, float a1, float a2,
                                      float& m00, float& m01, float& m10, float& m11)
{
    float c00 = -a1, c01 = 1.f, c10 = -a2, c11 = 0.f;
    float r00 = 1.f, r01 = 0.f, r10 = 0.f, r11 = 1.f;
    int e = n;
    while (e) {
        if (e & 1) {
            float t00 = r00*c00 + r01*c10, t01 = r00*c01 + r01*c11;
            float t10 = r10*c00 + r11*c10, t11 = r10*c01 + r11*c11;
            r00 = t00; r01 = t01; r10 = t10; r11 = t11;
        }
        e >>= 1;
        if (e) {
            float t00 = c00*c00 + c01*c10, t01 = c00*c01 + c01*c11;
            float t10 = c10*c00 + c11*c10, t11 = c10*c01 + c11*c11;
            c00 = t00; c01 = t01; c10 = t10; c11 = t11;
        }
    }
    m00 = r00; m01 = r01; m10 = r10; m11 = r11;
}

// ============================================================================
// radix-4 in-place FFT, N=4096. Twiddles from per-stage contiguous tables:
// level L has s=1<<(10-2L); fwd stage st -> level st, inv stage st -> 5-st.
// Entry: twk[LVL_OFF[L]+j] = W_N^{k*(j<<2L)}  (coalesced: lanes = consecutive j)
// ============================================================================
template<bool INV>
__device__ __forceinline__ void fft4096(float* sRe, float* sIm)
{
    const int tid = threadIdx.x;
    #pragma unroll 1
    for (int st = 0; st < 6; ++st) {
        const int lvl = INV ? (5 - st) : st;
        const int s   = 1 << (10 - 2 * lvl);
        const int off = LVL_OFF[lvl];
        #pragma unroll
        for (int m = 0; m < BF_PER; ++m) {
            const int bf = tid + FFT_THREADS * m;
            const int j  = bf & (s - 1);
            const int base = ((bf - j) << 2) + j;
            const int p0 = SM_PAD(base);
            const int p1 = SM_PAD(base + s);
            const int p2 = SM_PAD(base + 2 * s);
            const int p3 = SM_PAD(base + 3 * s);
            float ar = sRe[p0], ai = sIm[p0];
            float br = sRe[p1], bi = sIm[p1];
            float cr = sRe[p2], ci = sIm[p2];
            float dr = sRe[p3], di = sIm[p3];
            const int ti = off + j;          // coalesced across lanes
            const float2 w1 = g_tw1[ti];
            const float2 w2 = g_tw2[ti];
            const float2 w3 = g_tw3[ti];
            if (INV) {
                float t;
                t = br*w1.x + bi*w1.y;  bi = bi*w1.x - br*w1.y;  br = t;
                t = cr*w2.x + ci*w2.y;  ci = ci*w2.x - cr*w2.y;  cr = t;
                t = dr*w3.x + di*w3.y;  di = di*w3.x - dr*w3.y;  dr = t;
                float t0r = ar+cr, t0i = ai+ci, t1r = ar-cr, t1i = ai-ci;
                float t2r = br+dr, t2i = bi+di, t3r = br-dr, t3i = bi-di;
                sRe[p0] = t0r + t2r;  sIm[p0] = t0i + t2i;
                sRe[p1] = t1r - t3i;  sIm[p1] = t1i + t3r;
                sRe[p2] = t0r - t2r;  sIm[p2] = t0i - t2i;
                sRe[p3] = t1r + t3i;  sIm[p3] = t1i - t3r;
            } else {
                float t0r = ar+cr, t0i = ai+ci, t1r = ar-cr, t1i = ai-ci;
                float t2r = br+dr, t2i = bi+di, t3r = br-dr, t3i = bi-di;
                float Br = t1r + t3i, Bi = t1i - t3r;
                float Cr = t0r - t2r, Ci = t0i - t2i;
                float Dr = t1r - t3i, Di = t1i + t3r;
                sRe[p0] = t0r + t2r;           sIm[p0] = t0i + t2i;
                sRe[p1] = Br*w1.x - Bi*w1.y;   sIm[p1] = Br*w1.y + Bi*w1.x;
                sRe[p2] = Cr*w2.x - Ci*w2.y;   sIm[p2] = Cr*w2.y + Ci*w2.x;
                sRe[p3] = Dr*w3.x - Di*w3.y;   sIm[p3] = Dr*w3.y + Di*w3.x;
            }
        }
        __syncthreads();
    }
}

// ============================================================================
// init kernels
// ============================================================================
__global__ void twtab_init_kernel()
{
    const int L = blockIdx.x;
    const int s = 1 << (10 - 2 * L);
    const int shift = 2 * L;
    const int off = LVL_OFF[L];
    for (int j = threadIdx.x; j < s; j += blockDim.x) {
        int tb = j << shift;                 // < 1024, so 3*tb < 4096
        float sn, cs;
        sincospif((float)tb / 2048.0f, &sn, &cs);
        g_tw1[off + j] = make_float2(cs, -sn);
        sincospif((float)(2 * tb) / 2048.0f, &sn, &cs);
        g_tw2[off + j] = make_float2(cs, -sn);
        sincospif((float)(3 * tb) / 2048.0f, &sn, &cs);
        g_tw3[off + j] = make_float2(cs, -sn);
    }
}

__global__ void comb_kernel(const float* __restrict__ bf)
{
    int k = threadIdx.x;
    if (k >= G_TAPS) return;
    int d = k - HALO;
    int j0 = d < 0 ? -d : 0;
    int j1 = d < 0 ? (FIR_TAPS - 1) : (FIR_TAPS - 1 - d);
    float acc = 0.f;
    for (int j = j0; j <= j1; ++j)
        acc = fmaf(bf[j], bf[j + d], acc);
    g_comb[k] = acc;
}

// G in DIF output order: run the SAME forward FFT on circularly-placed g.
__global__ __launch_bounds__(FFT_THREADS)
void gfft_init_kernel()
{
    __shared__ float sRe[FFT_N + 256], sIm[FFT_N + 256];
    const int tid = threadIdx.x;
    #pragma unroll
    for (int m = 0; m < EL_PER; ++m) {
        int i = tid + FFT_THREADS * m;
        float v = 0.f;
        if (i <= HALO)                 v = g_comb[HALO + i];
        else if (i >= FFT_N - HALO)    v = g_comb[HALO - (FFT_N - i)];
        sRe[SM_PAD(i)] = v;
        sIm[SM_PAD(i)] = 0.f;
    }
    __syncthreads();
    fft4096<false>(sRe, sIm);
    #pragma unroll
    for (int m = 0; m < EL_PER; ++m) {
        int i = tid + FFT_THREADS * m;
        g_Grev[i] = sRe[SM_PAD(i)] * (1.0f / (float)FFT_N);
    }
}

// ============================================================================
// IIR pipeline (identical to the 1095.8us pass)
// ============================================================================
__global__ __launch_bounds__(256)
void transpose_kernel(const float* __restrict__ x)
{
    __shared__ float tile[32][33];
    const int tbase = blockIdx.x * 32, rbase = blockIdx.y * 32;
    const int tx = threadIdx.x, ty = threadIdx.y;
    #pragma unroll
    for (int j = 0; j < 32; j += 8)
        tile[ty + j][tx] = x[(size_t)(rbase + ty + j) * T_LEN + tbase + tx];
    __syncthreads();
    #pragma unroll
    for (int j = 0; j < 32; j += 8)
        g_xTe[(size_t)(tbase + ty + j + EDGE) * N_ROWS + rbase + tx] = tile[tx][ty + j];
}

__global__ __launch_bounds__(N_ROWS)
void edge_ext_kernel()
{
    const int r = threadIdx.x;
    const float x0 = g_xTe[(size_t)EDGE * N_ROWS + r];
    const float xL = g_xTe[(size_t)(T_LEN - 1 + EDGE) * N_ROWS + r];
    #pragma unroll
    for (int e = 0; e < EDGE; ++e)
        g_xTe[(size_t)e * N_ROWS + r] =
            2.0f * x0 - g_xTe[(size_t)(2 * EDGE - e) * N_ROWS + r];
    #pragma unroll
    for (int e = 0; e < EDGE; ++e) {
        int u = T_LEN + e;
        g_xTe[(size_t)(TEXT - EDGE + e) * N_ROWS + r] =
            2.0f * xL - g_xTe[(size_t)(2 * T_LEN - 2 - u + EDGE) * N_ROWS + r];
    }
}

__global__ __launch_bounds__(256)
void iir_phase1_fwd(const float* __restrict__ b, const float* __restrict__ a)
{
    const int w = (blockIdx.x * 256 + threadIdx.x) >> 5;
    const int lane = threadIdx.x & 31;
    const int p = w % P_CH, rg = w / P_CH, r = rg * 32 + lane;
    const float b0 = b[0], b1 = b[1], b2 = b[2], a1 = a[1], a2 = a[2];
    const int s = p * L_CH, len = chunk_len(s);

    float z1 = 0.f, z2 = 0.f, y;
    int i = s;
    const int e8 = s + (len & ~7);
    for (; i < e8; i += 8) {
        float xb[8];
        #pragma unroll
        for (int u = 0; u < 8; ++u) xb[u] = g_xTe[(size_t)(i + u) * N_ROWS + r];
        #pragma unroll
        for (int u = 0; u < 8; ++u) iir_step(xb[u], z1, z2, b0, b1, b2, a1, a2, y);
    }
    for (; i < s + len; ++i)
        iir_step(g_xTe[(size_t)i * N_ROWS + r], z1, z2, b0, b1, b2, a1, a2, y);
    g_V1[p * N_ROWS + r] = z1;
    g_V2[p * N_ROWS + r] = z2;
}

__global__ __launch_bounds__(P_CH)
void iir_scan_par(const float* __restrict__ a, const float* __restrict__ zi, int backward)
{
    __shared__ float sm00[P_CH], sm01[P_CH], sm10[P_CH], sm11[P_CH];
    __shared__ float sv1[P_CH], sv2[P_CH];
    const int row = blockIdx.x, q = threadIdx.x;
    const int c = backward ? (P_CH - 1 - q) : q;
    const float a1 = a[1], a2 = a[2];

    float m00, m01, m10, m11;
    a_pow(chunk_len(c * L_CH), a1, a2, m00, m01, m10, m11);
    float v1 = g_V1[c * N_ROWS + row], v2 = g_V2[c * N_ROWS + row];
    sm00[q] = m00; sm01[q] = m01; sm10[q] = m10; sm11[q] = m11;
    sv1[q] = v1; sv2[q] = v2;
    __syncthreads();

    #pragma unroll
    for (int d = 1; d < P_CH; d <<= 1) {
        float q00 = 0.f, q01 = 0.f, q10 = 0.f, q11 = 0.f, qv1 = 0.f, qv2 = 0.f;
        if (q >= d) {
            q00 = sm00[q-d]; q01 = sm01[q-d]; q10 = sm10[q-d]; q11 = sm11[q-d];
            qv1 = sv1[q-d]; qv2 = sv2[q-d];
        }
        __syncthreads();
        if (q >= d) {
            float n00 = m00*q00 + m01*q10, n01 = m00*q01 + m01*q11;
            float n10 = m10*q00 + m11*q10, n11 = m10*q01 + m11*q11;
            float nv1 = m00*qv1 + m01*qv2 + v1;
            float nv2 = m10*qv1 + m11*qv2 + v2;
            m00 = n00; m01 = n01; m10 = n10; m11 = n11; v1 = nv1; v2 = nv2;
            sm00[q] = m00; sm01[q] = m01; sm10[q] = m10; sm11[q] = m11;
            sv1[q] = v1; sv2[q] = v2;
        }
        __syncthreads();
    }

    float e0 = backward ? g_yfT[(size_t)(TEXT - 1) * N_ROWS + row] : g_xTe[row];
    float zi1 = zi[0] * e0, zi2 = zi[1] * e0;
    float z1, z2;
    if (q == 0) { z1 = zi1; z2 = zi2; }
    else {
        z1 = sm00[q-1]*zi1 + sm01[q-1]*zi2 + sv1[q-1];
        z2 = sm10[q-1]*zi1 + sm11[q-1]*zi2 + sv2[q-1];
    }
    g_Z1[c * N_ROWS + row] = z1;
    g_Z2[c * N_ROWS + row] = z2;
}

__global__ __launch_bounds__(256)
void iir_mid(const float* __restrict__ b, const float* __restrict__ a)
{
    const int w = (blockIdx.x * 256 + threadIdx.x) >> 5;
    const int lane = threadIdx.x & 31;
    const int p = w % P_CH, rg = w / P_CH, r = rg * 32 + lane;
    const float b0 = b[0], b1 = b[1], b2 = b[2], a1 = a[1], a2 = a[2];
    const int s = p * L_CH, len = chunk_len(s);

    float z1 = g_Z1[p * N_ROWS + r], z2 = g_Z2[p * N_ROWS + r], y;
    int i = s;
    const int e8 = s + (len & ~7);
    for (; i < e8; i += 8) {
        float xb[8];
        #pragma unroll
        for (int u = 0; u < 8; ++u) xb[u] = g_xTe[(size_t)(i + u) * N_ROWS + r];
        #pragma unroll
        for (int u = 0; u < 8; ++u) {
            iir_step(xb[u], z1, z2, b0, b1, b2, a1, a2, y);
            g_yfT[(size_t)(i + u) * N_ROWS + r] = y;
        }
    }
    for (; i < s + len; ++i) {
        iir_step(g_xTe[(size_t)i * N_ROWS + r], z1, z2, b0, b1, b2, a1, a2, y);
        g_yfT[(size_t)i * N_ROWS + r] = y;
    }

    float bz1 = 0.f, bz2 = 0.f;
    int j = s + len - 1;
    const int cnt8 = len & ~7;
    for (int c = 0; c < cnt8; c += 8, j -= 8) {
        float xb[8];
        #pragma unroll
        for (int u = 0; u < 8; ++u) xb[u] = g_yfT[(size_t)(j - u) * N_ROWS + r];
        #pragma unroll
        for (int u = 0; u < 8; ++u) iir_step(xb[u], bz1, bz2, b0, b1, b2, a1, a2, y);
    }
    for (; j >= s; --j)
        iir_step(g_yfT[(size_t)j * N_ROWS + r], bz1, bz2, b0, b1, b2, a1, a2, y);
    g_V1[p * N_ROWS + r] = bz1;
    g_V2[p * N_ROWS + r] = bz2;
}

__global__ __launch_bounds__(256)
void iir_phase2_bwd(const float* __restrict__ b, const float* __restrict__ a)
{
    __shared__ float stile[8][32][33];
    const int wib = threadIdx.x >> 5;
    float (*sS)[33] = stile[wib];

    const int w = (blockIdx.x * 256 + threadIdx.x) >> 5;
    const int lane = threadIdx.x & 31;
    const int p = w % P_CH, rg = w / P_CH, r = rg * 32 + lane;
    const int rowbase = rg * 32;
    const float b0 = b[0], b1 = b[1], b2 = b[2], a1 = a[1], a2 = a[2];
    const int s = p * L_CH, len = chunk_len(s);

    float z1 = g_Z1[p * N_ROWS + r], z2 = g_Z2[p * N_ROWS + r], y;
    int i = s + len - 1;
    int remaining = len;
    while (remaining > 0) {
        const int itop = i;
        int cnt = remaining < 32 ? remaining : 32;
        if (cnt == 32) {
            #pragma unroll 1
            for (int c = 0; c < 32; c += 8) {
                float xb[8];
                #pragma unroll
                for (int u = 0; u < 8; ++u) xb[u] = g_yfT[(size_t)(i - u) * N_ROWS + r];
                #pragma unroll
                for (int u = 0; u < 8; ++u) {
                    iir_step(xb[u], z1, z2, b0, b1, b2, a1, a2, y);
                    sS[lane][c + u] = y;
                }
                i -= 8;
            }
        } else {
            for (int c = 0; c < cnt; ++c, --i) {
                iir_step(g_yfT[(size_t)i * N_ROWS + r], z1, z2, b0, b1, b2, a1, a2, y);
                sS[lane][c] = y;
            }
        }
        remaining -= cnt;
        __syncwarp();
        const int ttop = itop - EDGE;
        const int t2 = ttop - lane;
        const bool ok = (lane < cnt) && (t2 >= 0) && (t2 < T_LEN);
        #pragma unroll 4
        for (int rr = 0; rr < 32; ++rr) {
            float v = sS[rr][lane];
            if (ok) g_mid[(size_t)(rowbase + rr) * T_LEN + t2] = v;
        }
        __syncwarp();
    }
}

// ============================================================================
// FFT overlap-save conv: block = (segment, row-pair). Two rows packed re/im.
// ============================================================================
__global__ __launch_bounds__(FFT_THREADS)
void fft_conv_kernel(float* __restrict__ out)
{
    __shared__ float sRe[FFT_N + 256], sIm[FFT_N + 256];
    const int tid = threadIdx.x;
    const int seg = blockIdx.x;
    const int rp  = blockIdx.y;
    const int row0 = 2 * rp, row1 = 2 * rp + 1;
    const int seg_start = seg * SEG_L;
    const float* x0 = g_mid + (size_t)row0 * T_LEN;
    const float* x1 = g_mid + (size_t)row1 * T_LEN;

    #pragma unroll
    for (int m = 0; m < EL_PER; ++m) {
        int p = tid + FFT_THREADS * m;
        int u = seg_start - HALO + p;
        int pp = SM_PAD(p);
        sRe[pp] = odd_ext_load(x0, u);
        sIm[pp] = odd_ext_load(x1, u);
    }
    __syncthreads();

    fft4096<false>(sRe, sIm);

    #pragma unroll
    for (int m = 0; m < EL_PER; ++m) {
        int i = tid + FFT_THREADS * m;
        float gv = g_Grev[i];
        int pp = SM_PAD(i);
        sRe[pp] *= gv;
        sIm[pp] *= gv;
    }
    __syncthreads();

    fft4096<true>(sRe, sIm);

    #pragma unroll
    for (int m = 0; m < EL_PER; ++m) {
        int p = tid + FFT_THREADS * m;
        if (p >= HALO && p < HALO + SEG_L) {
            int t = seg_start + p - HALO;
            if (t < T_LEN) {
                int pp = SM_PAD(p);
                out[(size_t)row0 * T_LEN + t] = sRe[pp];
                out[(size_t)row1 * T_LEN + t] = sIm[pp];
            }
        }
    }
}

// ============================================================================
// Inputs: x, b_notch(3), a_notch(3), zi_notch(2), b_fir(151), zi_fir (unused)
// ============================================================================
extern "C" void kernel_launch(void* const* d_in, const int* in_sizes, int n_in,
                              void* d_out, int out_size)
{
    const float* x  = (const float*)d_in[0];
    const float* bn = (const float*)d_in[1];
    const float* an = (const float*)d_in[2];
    const float* zn = (const float*)d_in[3];
    const float* bf = (const float*)d_in[4];
    float* out = (float*)d_out;

    twtab_init_kernel<<<6, 256>>>();                     // 0
    comb_kernel<<<1, 320>>>(bf);                         // 1
    gfft_init_kernel<<<1, FFT_THREADS>>>();              // 2

    dim3 tgrid(T_LEN / 32, N_ROWS / 32);
    transpose_kernel<<<tgrid, dim3(32, 8)>>>(x);         // 3
    edge_ext_kernel<<<1, N_ROWS>>>();                    // 4

    iir_phase1_fwd<<<IIR_BLOCKS, 256>>>(bn, an);         // 5
    iir_scan_par<<<N_ROWS, P_CH>>>(an, zn, 0);           // 6
    iir_mid<<<IIR_BLOCKS, 256>>>(bn, an);                // 7
    iir_scan_par<<<N_ROWS, P_CH>>>(an, zn, 1);           // 8
    iir_phase2_bwd<<<IIR_BLOCKS, 256>>>(bn, an);         // 9

    dim3 fgrid(NSEG, N_ROWS / 2);
    fft_conv_kernel<<<fgrid, FFT_THREADS>>>(out);        // 10
}